// round 2
// baseline (speedup 1.0000x reference)
#include <cuda_runtime.h>
#include <math.h>

#define Bb 4
#define Hh 96
#define Ww 96
#define Cc 256
#define Ff 256

typedef unsigned long long u64;

__device__ __forceinline__ u64 ffma2(u64 a, u64 b, u64 c) {
    u64 d;
    asm("fma.rn.f32x2 %0, %1, %2, %3;" : "=l"(d) : "l"(a), "l"(b), "l"(c));
    return d;
}
__device__ __forceinline__ u64 pack2(float lo, float hi) {
    u64 d;
    asm("mov.b64 %0, {%1, %2};" : "=l"(d) : "f"(lo), "f"(hi));
    return d;
}
__device__ __forceinline__ void unpack2(u64 v, float& lo, float& hi) {
    asm("mov.b64 {%0, %1}, %2;" : "=f"(lo), "=f"(hi) : "l"(v));
}

// scratch for offset-conv output: per pixel 27 values:
// [0..8]=dy, [9..17]=dx, [18..26]=sigmoid(mask)
__device__ float g_om[Bb * Hh * Ww * 27];

// ---------------------------------------------------------------------------
// Kernel A: 3x3 SAME conv, C=256 -> 27, + bias, sigmoid on channels 18..26.
// ---------------------------------------------------------------------------
__global__ __launch_bounds__(128) void offset_conv_kernel(
    const float* __restrict__ x, const float* __restrict__ w_off,
    const float* __restrict__ b_off)
{
    __shared__ __align__(16) float xs_s[16][36];  // [c_chunk][px] padded
    __shared__ float ws_s[16][28];                // [c_chunk][oc]

    const int w0 = blockIdx.x * 32;
    const int h  = blockIdx.y;
    const int b  = blockIdx.z;
    const int tid = threadIdx.x;
    const int oc = tid & 31;
    const int pg = tid >> 5;   // 0..3

    u64 accp[4];
#pragma unroll
    for (int j = 0; j < 4; j++) accp[j] = 0ULL;

    for (int t = 0; t < 9; t++) {
        const int ky = t / 3, kx = t % 3;
        const int y = h + ky - 1;
        if (y < 0 || y >= Hh) continue;   // uniform across block -> sync-safe
        const float* xrow = x + ((size_t)(b * Hh + y) * Ww) * Cc;

        for (int cc = 0; cc < 16; cc++) {
            __syncthreads();
            {
                const int ci  = tid & 15;
                const int pxg = tid >> 4;  // 0..7
#pragma unroll
                for (int j = 0; j < 4; j++) {
                    const int px = pxg + j * 8;
                    const int xc = w0 + px + kx - 1;
                    float v = 0.f;
                    if (xc >= 0 && xc < Ww) v = xrow[xc * Cc + cc * 16 + ci];
                    xs_s[ci][px] = v;
                }
            }
            for (int idx = tid; idx < 16 * 27; idx += 128) {
                const int ci = idx / 27, o = idx % 27;
                ws_s[ci][o] = w_off[(t * Cc + cc * 16 + ci) * 27 + o];
            }
            __syncthreads();

            if (oc < 27) {
#pragma unroll
                for (int ci = 0; ci < 16; ci++) {
                    const float wv = ws_s[ci][oc];
                    const u64 wvp = pack2(wv, wv);
                    const float* xr = &xs_s[ci][pg * 8];
                    const ulonglong2 a  = *(const ulonglong2*)(xr);
                    const ulonglong2 c2 = *(const ulonglong2*)(xr + 4);
                    accp[0] = ffma2(a.x,  wvp, accp[0]);
                    accp[1] = ffma2(a.y,  wvp, accp[1]);
                    accp[2] = ffma2(c2.x, wvp, accp[2]);
                    accp[3] = ffma2(c2.y, wvp, accp[3]);
                }
            }
        }
    }

    if (oc < 27) {
        const float bo = b_off[oc];
        float av[8];
#pragma unroll
        for (int j = 0; j < 4; j++) unpack2(accp[j], av[2 * j], av[2 * j + 1]);
#pragma unroll
        for (int j = 0; j < 8; j++) {
            float v = av[j] + bo;
            if (oc >= 18) v = 1.f / (1.f + expf(-v));   // sigmoid for mask
            const int px = pg * 8 + j;
            g_om[((size_t)((b * Hh + h) * Ww + w0 + px)) * 27 + oc] = v;
        }
    }
}

// ---------------------------------------------------------------------------
// Kernel B: deformable sampling + [32 px, 2304] x [2304, 256] GEMM per block.
// blockDim=256: tx = tid&63 -> f group (4 f = 2 f32x2 pairs), py = tid>>6.
// Inner product in packed f32x2: per ci, 1 LDS.128 (w pair) + 8 LDS.64
// (pre-duplicated sampled values, warp-broadcast) + 16 FFMA2.
// ---------------------------------------------------------------------------
__global__ __launch_bounds__(256, 3) void dcn_main_kernel(
    const float* __restrict__ x, const float* __restrict__ w_conv,
    const float* __restrict__ b_conv, float* __restrict__ out)
{
    __shared__ __align__(16) float w_s[16 * 256];   // [ci][f]   16 KB
    __shared__ __align__(16) u64 s_d[16 * 33];      // [ci][px] dup-packed, 4.2 KB
    __shared__ float4 mw[288];                      // per (px,tap): 4 corner weights
    __shared__ int4   mi[288];                      // per (px,tap): 4 corner bases

    const int w0 = blockIdx.x * 32;
    const int h  = blockIdx.y;
    const int b  = blockIdx.z;
    const int tid = threadIdx.x;

    // ---- bilinear meta for 32 px x 9 taps ----
    for (int e = tid; e < 288; e += 256) {
        const int px = e / 9, k = e % 9;
        const int p = (b * Hh + h) * Ww + w0 + px;
        const float* om = g_om + (size_t)p * 27;
        const float dy = om[k], dx = om[9 + k], mask = om[18 + k];
        const int ky = k / 3, kx = k % 3;
        const float ys = (float)(h + ky - 1) + dy;
        const float xs = (float)(w0 + px + kx - 1) + dx;
        const float y0f = floorf(ys), x0f = floorf(xs);
        const float wy1 = ys - y0f, wx1 = xs - x0f;
        const float wy0 = 1.f - wy1, wx0 = 1.f - wx1;
        const int y0 = (int)y0f, x0i = (int)x0f;
        const int y1 = y0 + 1,   x1i = x0i + 1;
        const bool vy0 = (y0  >= 0) && (y0  < Hh);
        const bool vy1 = (y1  >= 0) && (y1  < Hh);
        const bool vx0 = (x0i >= 0) && (x0i < Ww);
        const bool vx1 = (x1i >= 0) && (x1i < Ww);
        const float w00 = (vy0 && vx0) ? wy0 * wx0 * mask : 0.f;
        const float w01 = (vy0 && vx1) ? wy0 * wx1 * mask : 0.f;
        const float w10 = (vy1 && vx0) ? wy1 * wx0 * mask : 0.f;
        const float w11 = (vy1 && vx1) ? wy1 * wx1 * mask : 0.f;
        const int y0c = min(max(y0, 0), Hh - 1), y1c = min(max(y1, 0), Hh - 1);
        const int x0c = min(max(x0i, 0), Ww - 1), x1c = min(max(x1i, 0), Ww - 1);
        const int r0 = (b * Hh + y0c) * Ww, r1 = (b * Hh + y1c) * Ww;
        mw[e] = make_float4(w00, w01, w10, w11);
        mi[e] = make_int4((r0 + x0c) * Cc, (r0 + x1c) * Cc,
                          (r1 + x0c) * Cc, (r1 + x1c) * Cc);
    }
    __syncthreads();

    u64 acc[8][2];
#pragma unroll
    for (int i = 0; i < 8; i++) { acc[i][0] = 0ULL; acc[i][1] = 0ULL; }

    const int tx  = tid & 63;    // f group (4 f)
    const int py  = tid >> 6;    // pixel group (0..3)
    const int cis = tid & 15;    // staging: channel-in-chunk
    const int pxg = tid >> 4;    // staging: pixel base (0..15)

    for (int k = 0; k < 9; k++) {
        for (int cc = 0; cc < 16; cc++) {
            __syncthreads();
            // ---- stage w_conv chunk: 16 c x 256 f ----
            {
                const float4* wsrc =
                    (const float4*)(w_conv + (size_t)(k * Cc + cc * 16) * Ff);
                float4* wdst = (float4*)w_s;
#pragma unroll
                for (int i = 0; i < 4; i++)
                    wdst[tid + i * 256] = wsrc[tid + i * 256];
            }
            // ---- stage sampled tile: 16 c x 32 px, duplicated f32x2 ----
            {
                const int c = cc * 16 + cis;
#pragma unroll
                for (int j = 0; j < 2; j++) {
                    const int px = pxg + j * 16;
                    const int e = px * 9 + k;
                    const float4 wv = mw[e];
                    const int4   a  = mi[e];
                    float v = wv.x * x[a.x + c];
                    v += wv.y * x[a.y + c];
                    v += wv.z * x[a.z + c];
                    v += wv.w * x[a.w + c];
                    s_d[cis * 33 + px] = pack2(v, v);
                }
            }
            __syncthreads();
            // ---- FFMA2 core: 16 c x (8 px x 2 f-pairs) per thread ----
#pragma unroll
            for (int ci = 0; ci < 16; ci++) {
                const ulonglong2 wp = *(const ulonglong2*)&w_s[ci * 256 + tx * 4];
                const u64* sr = &s_d[ci * 33 + py * 8];
#pragma unroll
                for (int i = 0; i < 8; i++) {
                    const u64 sv = sr[i];
                    acc[i][0] = ffma2(sv, wp.x, acc[i][0]);
                    acc[i][1] = ffma2(sv, wp.y, acc[i][1]);
                }
            }
        }
    }

    // ---- epilogue: + bias, store ----
    const float4 bc = *(const float4*)(b_conv + tx * 4);
    const size_t base = ((size_t)((b * Hh + h) * Ww + w0)) * Ff;
#pragma unroll
    for (int i = 0; i < 8; i++) {
        const int px = py * 8 + i;
        float4 o;
        unpack2(acc[i][0], o.x, o.y);
        unpack2(acc[i][1], o.z, o.w);
        o.x += bc.x; o.y += bc.y; o.z += bc.z; o.w += bc.w;
        *(float4*)(out + base + (size_t)px * Ff + tx * 4) = o;
    }
}

// ---------------------------------------------------------------------------
extern "C" void kernel_launch(void* const* d_in, const int* in_sizes, int n_in,
                              void* d_out, int out_size)
{
    (void)in_sizes; (void)n_in; (void)out_size;
    const float* x      = (const float*)d_in[0];
    const float* w_off  = (const float*)d_in[1];
    const float* b_off  = (const float*)d_in[2];
    const float* w_conv = (const float*)d_in[3];
    const float* b_conv = (const float*)d_in[4];
    float* out = (float*)d_out;

    dim3 gA(3, 96, 4);
    offset_conv_kernel<<<gA, 128>>>(x, w_off, b_off);
    dim3 gB(3, 96, 4);
    dcn_main_kernel<<<gB, 256>>>(x, w_conv, b_conv, out);
}

// round 3
// speedup vs baseline: 1.0858x; 1.0858x over previous
#include <cuda_runtime.h>
#include <math.h>

#define Bb 4
#define Hh 96
#define Ww 96
#define Cc 256
#define Ff 256

typedef unsigned long long u64;

__device__ __forceinline__ u64 ffma2(u64 a, u64 b, u64 c) {
    u64 d;
    asm("fma.rn.f32x2 %0, %1, %2, %3;" : "=l"(d) : "l"(a), "l"(b), "l"(c));
    return d;
}
__device__ __forceinline__ u64 pack2(float lo, float hi) {
    u64 d;
    asm("mov.b64 %0, {%1, %2};" : "=l"(d) : "f"(lo), "f"(hi));
    return d;
}
__device__ __forceinline__ void unpack2(u64 v, float& lo, float& hi) {
    asm("mov.b64 {%0, %1}, %2;" : "=f"(lo), "=f"(hi) : "l"(v));
}

// scratch for offset-conv output: per pixel 27 values:
// [0..8]=dy, [9..17]=dx, [18..26]=sigmoid(mask)
__device__ float g_om[Bb * Hh * Ww * 27];

// ---------------------------------------------------------------------------
// Kernel A: 3x3 SAME conv, C=256 -> 27, + bias, sigmoid on channels 18..26.
// ---------------------------------------------------------------------------
__global__ __launch_bounds__(128) void offset_conv_kernel(
    const float* __restrict__ x, const float* __restrict__ w_off,
    const float* __restrict__ b_off)
{
    __shared__ __align__(16) float xs_s[16][36];
    __shared__ float ws_s[16][28];

    const int w0 = blockIdx.x * 32;
    const int h  = blockIdx.y;
    const int b  = blockIdx.z;
    const int tid = threadIdx.x;
    const int oc = tid & 31;
    const int pg = tid >> 5;

    u64 accp[4];
#pragma unroll
    for (int j = 0; j < 4; j++) accp[j] = 0ULL;

    for (int t = 0; t < 9; t++) {
        const int ky = t / 3, kx = t % 3;
        const int y = h + ky - 1;
        if (y < 0 || y >= Hh) continue;   // uniform across block -> sync-safe
        const float* xrow = x + ((size_t)(b * Hh + y) * Ww) * Cc;

        for (int cc = 0; cc < 16; cc++) {
            __syncthreads();
            {
                const int ci  = tid & 15;
                const int pxg = tid >> 4;
#pragma unroll
                for (int j = 0; j < 4; j++) {
                    const int px = pxg + j * 8;
                    const int xc = w0 + px + kx - 1;
                    float v = 0.f;
                    if (xc >= 0 && xc < Ww) v = xrow[xc * Cc + cc * 16 + ci];
                    xs_s[ci][px] = v;
                }
            }
            for (int idx = tid; idx < 16 * 27; idx += 128) {
                const int ci = idx / 27, o = idx % 27;
                ws_s[ci][o] = w_off[(t * Cc + cc * 16 + ci) * 27 + o];
            }
            __syncthreads();

            if (oc < 27) {
#pragma unroll
                for (int ci = 0; ci < 16; ci++) {
                    const float wv = ws_s[ci][oc];
                    const u64 wvp = pack2(wv, wv);
                    const float* xr = &xs_s[ci][pg * 8];
                    const ulonglong2 a  = *(const ulonglong2*)(xr);
                    const ulonglong2 c2 = *(const ulonglong2*)(xr + 4);
                    accp[0] = ffma2(a.x,  wvp, accp[0]);
                    accp[1] = ffma2(a.y,  wvp, accp[1]);
                    accp[2] = ffma2(c2.x, wvp, accp[2]);
                    accp[3] = ffma2(c2.y, wvp, accp[3]);
                }
            }
        }
    }

    if (oc < 27) {
        const float bo = b_off[oc];
        float av[8];
#pragma unroll
        for (int j = 0; j < 4; j++) unpack2(accp[j], av[2 * j], av[2 * j + 1]);
#pragma unroll
        for (int j = 0; j < 8; j++) {
            float v = av[j] + bo;
            if (oc >= 18) v = 1.f / (1.f + expf(-v));
            const int px = pg * 8 + j;
            g_om[((size_t)((b * Hh + h) * Ww + w0 + px)) * 27 + oc] = v;
        }
    }
}

// ---------------------------------------------------------------------------
// Kernel B: deformable sampling + [32 px, 2304] x [2304, 256] GEMM per block.
// 128 threads: lane = f-group (8 f: 4*lane..+3 and 128+4*lane..+3),
//              warp  = px-group (8 px). Thread tile 8 px x 8 f in f32x2.
// Per warp per ci: 2 conflict-free LDS.128 (w) + 4 broadcast LDS.128 (s)
//                  = 12 wavefronts vs 32 FFMA2 -> fma-bound.
// ---------------------------------------------------------------------------
__global__ __launch_bounds__(128, 4) void dcn_main_kernel(
    const float* __restrict__ x, const float* __restrict__ w_conv,
    const float* __restrict__ b_conv, float* __restrict__ out)
{
    __shared__ __align__(16) float w_s[32 * 256];   // [ci][f]   32 KB
    __shared__ __align__(16) u64 s_d[32 * 34];      // [ci][px] dup-packed, 8.5 KB
    __shared__ float4 mw[32];                       // per px (current tap)
    __shared__ int4   mi[32];

    const int w0 = blockIdx.x * 32;
    const int h  = blockIdx.y;
    const int b  = blockIdx.z;
    const int tid  = threadIdx.x;
    const int lane = tid & 31;
    const int py   = tid >> 5;      // warp id = px group

    u64 acc[8][4];
#pragma unroll
    for (int i = 0; i < 8; i++)
#pragma unroll
        for (int j = 0; j < 4; j++) acc[i][j] = 0ULL;

    for (int k = 0; k < 9; k++) {
        // ---- bilinear meta for 32 px at tap k (warp 0) ----
        // Safe without extra sync: previous round's stage (the only meta
        // reader) completed before the preceding __syncthreads().
        if (tid < 32) {
            const int px = tid;
            const int p = (b * Hh + h) * Ww + w0 + px;
            const float* om = g_om + (size_t)p * 27;
            const float dy = om[k], dx = om[9 + k], mask = om[18 + k];
            const int ky = k / 3, kx = k % 3;
            const float ys = (float)(h + ky - 1) + dy;
            const float xs = (float)(w0 + px + kx - 1) + dx;
            const float y0f = floorf(ys), x0f = floorf(xs);
            const float wy1 = ys - y0f, wx1 = xs - x0f;
            const float wy0 = 1.f - wy1, wx0 = 1.f - wx1;
            const int y0 = (int)y0f, x0i = (int)x0f;
            const int y1 = y0 + 1,   x1i = x0i + 1;
            const bool vy0 = (y0  >= 0) && (y0  < Hh);
            const bool vy1 = (y1  >= 0) && (y1  < Hh);
            const bool vx0 = (x0i >= 0) && (x0i < Ww);
            const bool vx1 = (x1i >= 0) && (x1i < Ww);
            const float c00 = (vy0 && vx0) ? wy0 * wx0 * mask : 0.f;
            const float c01 = (vy0 && vx1) ? wy0 * wx1 * mask : 0.f;
            const float c10 = (vy1 && vx0) ? wy1 * wx0 * mask : 0.f;
            const float c11 = (vy1 && vx1) ? wy1 * wx1 * mask : 0.f;
            const int y0c = min(max(y0, 0), Hh - 1), y1c = min(max(y1, 0), Hh - 1);
            const int x0c = min(max(x0i, 0), Ww - 1), x1c = min(max(x1i, 0), Ww - 1);
            const int r0 = (b * Hh + y0c) * Ww, r1 = (b * Hh + y1c) * Ww;
            mw[px] = make_float4(c00, c01, c10, c11);
            mi[px] = make_int4((r0 + x0c) * Cc, (r0 + x1c) * Cc,
                               (r1 + x0c) * Cc, (r1 + x1c) * Cc);
        }

        for (int cc = 0; cc < 8; cc++) {   // 8 chunks of 32 channels
            __syncthreads();
            // ---- stage w_conv chunk: 32 c x 256 f (32 KB) ----
            {
                const float4* wsrc =
                    (const float4*)(w_conv + (size_t)(k * Cc + cc * 32) * Ff);
                float4* wdst = (float4*)w_s;
#pragma unroll
                for (int i = 0; i < 16; i++)
                    wdst[tid + i * 128] = wsrc[tid + i * 128];
            }
            // ---- stage sampled tile: 32 c x 32 px, duplicated f32x2 ----
            {
                const int c = cc * 32 + lane;    // lane = channel in chunk
#pragma unroll
                for (int j = 0; j < 8; j++) {
                    const int px = py * 8 + j;
                    const float4 wv = mw[px];
                    const int4   a  = mi[px];
                    float v = wv.x * x[a.x + c];
                    v += wv.y * x[a.y + c];
                    v += wv.z * x[a.z + c];
                    v += wv.w * x[a.w + c];
                    s_d[lane * 34 + px] = pack2(v, v);
                }
            }
            __syncthreads();
            // ---- FFMA2 core ----
#pragma unroll 8
            for (int ci = 0; ci < 32; ci++) {
                const ulonglong2 wa = *(const ulonglong2*)&w_s[ci * 256 + lane * 4];
                const ulonglong2 wb = *(const ulonglong2*)&w_s[ci * 256 + 128 + lane * 4];
                const u64* sr = &s_d[ci * 34 + py * 8];
                const ulonglong2 s01 = *(const ulonglong2*)(sr);
                const ulonglong2 s23 = *(const ulonglong2*)(sr + 2);
                const ulonglong2 s45 = *(const ulonglong2*)(sr + 4);
                const ulonglong2 s67 = *(const ulonglong2*)(sr + 6);
                u64 sv;
#define STEP(i, svv) \
                sv = (svv); \
                acc[i][0] = ffma2(sv, wa.x, acc[i][0]); \
                acc[i][1] = ffma2(sv, wa.y, acc[i][1]); \
                acc[i][2] = ffma2(sv, wb.x, acc[i][2]); \
                acc[i][3] = ffma2(sv, wb.y, acc[i][3]);
                STEP(0, s01.x) STEP(1, s01.y)
                STEP(2, s23.x) STEP(3, s23.y)
                STEP(4, s45.x) STEP(5, s45.y)
                STEP(6, s67.x) STEP(7, s67.y)
#undef STEP
            }
        }
    }

    // ---- epilogue: + bias, store (thread's f = 4*lane..+3 and 128+4*lane..+3)
    const float4 bc0 = *(const float4*)(b_conv + lane * 4);
    const float4 bc1 = *(const float4*)(b_conv + 128 + lane * 4);
    const size_t base = ((size_t)((b * Hh + h) * Ww + w0)) * Ff;
#pragma unroll
    for (int i = 0; i < 8; i++) {
        const int px = py * 8 + i;
        float4 o0, o1;
        unpack2(acc[i][0], o0.x, o0.y);
        unpack2(acc[i][1], o0.z, o0.w);
        unpack2(acc[i][2], o1.x, o1.y);
        unpack2(acc[i][3], o1.z, o1.w);
        o0.x += bc0.x; o0.y += bc0.y; o0.z += bc0.z; o0.w += bc0.w;
        o1.x += bc1.x; o1.y += bc1.y; o1.z += bc1.z; o1.w += bc1.w;
        float* op = out + base + (size_t)px * Ff;
        *(float4*)(op + lane * 4) = o0;
        *(float4*)(op + 128 + lane * 4) = o1;
    }
}

// ---------------------------------------------------------------------------
extern "C" void kernel_launch(void* const* d_in, const int* in_sizes, int n_in,
                              void* d_out, int out_size)
{
    (void)in_sizes; (void)n_in; (void)out_size;
    const float* x      = (const float*)d_in[0];
    const float* w_off  = (const float*)d_in[1];
    const float* b_off  = (const float*)d_in[2];
    const float* w_conv = (const float*)d_in[3];
    const float* b_conv = (const float*)d_in[4];
    float* out = (float*)d_out;

    dim3 gA(3, 96, 4);
    offset_conv_kernel<<<gA, 128>>>(x, w_off, b_off);
    dim3 gB(3, 96, 4);
    dcn_main_kernel<<<gB, 128>>>(x, w_conv, b_conv, out);
}

// round 5
// speedup vs baseline: 1.4512x; 1.3365x over previous
#include <cuda_runtime.h>
#include <cuda_bf16.h>
#include <math.h>
#include <stdint.h>

#define Bb 4
#define Hh 96
#define Ww 96
#define Cc 256
#define Ff 256

typedef unsigned long long u64;

// ===================== scalar helpers (kernel A) ============================
__device__ __forceinline__ u64 ffma2(u64 a, u64 b, u64 c) {
    u64 d;
    asm("fma.rn.f32x2 %0, %1, %2, %3;" : "=l"(d) : "l"(a), "l"(b), "l"(c));
    return d;
}
__device__ __forceinline__ u64 pack2(float lo, float hi) {
    u64 d;
    asm("mov.b64 %0, {%1, %2};" : "=l"(d) : "f"(lo), "f"(hi));
    return d;
}
__device__ __forceinline__ void unpack2(u64 v, float& lo, float& hi) {
    asm("mov.b64 {%0, %1}, %2;" : "=f"(lo), "=f"(hi) : "l"(v));
}

// ===================== mma.sync helpers =====================================
__device__ __forceinline__ uint32_t smem_u32(const void* p) {
    uint32_t a;
    asm("{ .reg .u64 t; cvta.to.shared.u64 t, %1; cvt.u32.u64 %0, t; }"
        : "=r"(a) : "l"(p));
    return a;
}
__device__ __forceinline__ void ldsm4(uint32_t* r, uint32_t addr) {
    asm volatile("ldmatrix.sync.aligned.m8n8.x4.shared.b16 {%0,%1,%2,%3}, [%4];"
        : "=r"(r[0]), "=r"(r[1]), "=r"(r[2]), "=r"(r[3]) : "r"(addr));
}
__device__ __forceinline__ void mma_bf16(float* d, const uint32_t* a,
                                         uint32_t b0, uint32_t b1) {
    asm volatile(
        "mma.sync.aligned.m16n8k16.row.col.f32.bf16.bf16.f32 "
        "{%0,%1,%2,%3}, {%4,%5,%6,%7}, {%8,%9}, {%0,%1,%2,%3};"
        : "+f"(d[0]), "+f"(d[1]), "+f"(d[2]), "+f"(d[3])
        : "r"(a[0]), "r"(a[1]), "r"(a[2]), "r"(a[3]), "r"(b0), "r"(b1));
}
// packed bf16x2 of (v0, v1): lo half = v0
__device__ __forceinline__ uint32_t cvt_bf16x2(float v0, float v1) {
    uint32_t d;
    asm("cvt.rn.bf16x2.f32 %0, %1, %2;" : "=r"(d) : "f"(v1), "f"(v0));
    return d;
}

// ===================== device scratch =======================================
__device__ float g_om[Bb * Hh * Ww * 27];          // dy[9], dx[9], sig(mask)[9]
// w_conv, bf16-split, layout [chunk=72][f=256][16 x bf16x2 along k]
__device__ uint32_t g_wbh[72 * 256 * 16];
__device__ uint32_t g_wbl[72 * 256 * 16];

// ===================== Kernel A: offset conv ================================
__global__ __launch_bounds__(128) void offset_conv_kernel(
    const float* __restrict__ x, const float* __restrict__ w_off,
    const float* __restrict__ b_off)
{
    __shared__ __align__(16) float xs_s[16][36];
    __shared__ float ws_s[16][28];

    const int w0 = blockIdx.x * 32;
    const int h  = blockIdx.y;
    const int b  = blockIdx.z;
    const int tid = threadIdx.x;
    const int oc = tid & 31;
    const int pg = tid >> 5;

    u64 accp[4];
#pragma unroll
    for (int j = 0; j < 4; j++) accp[j] = 0ULL;

    for (int t = 0; t < 9; t++) {
        const int ky = t / 3, kx = t % 3;
        const int y = h + ky - 1;
        if (y < 0 || y >= Hh) continue;
        const float* xrow = x + ((size_t)(b * Hh + y) * Ww) * Cc;

        for (int cc = 0; cc < 16; cc++) {
            __syncthreads();
            {
                const int ci  = tid & 15;
                const int pxg = tid >> 4;
#pragma unroll
                for (int j = 0; j < 4; j++) {
                    const int px = pxg + j * 8;
                    const int xc = w0 + px + kx - 1;
                    float v = 0.f;
                    if (xc >= 0 && xc < Ww) v = xrow[xc * Cc + cc * 16 + ci];
                    xs_s[ci][px] = v;
                }
            }
            for (int idx = tid; idx < 16 * 27; idx += 128) {
                const int ci = idx / 27, o = idx % 27;
                ws_s[ci][o] = w_off[(t * Cc + cc * 16 + ci) * 27 + o];
            }
            __syncthreads();

            if (oc < 27) {
#pragma unroll
                for (int ci = 0; ci < 16; ci++) {
                    const float wv = ws_s[ci][oc];
                    const u64 wvp = pack2(wv, wv);
                    const float* xr = &xs_s[ci][pg * 8];
                    const ulonglong2 a  = *(const ulonglong2*)(xr);
                    const ulonglong2 c2 = *(const ulonglong2*)(xr + 4);
                    accp[0] = ffma2(a.x,  wvp, accp[0]);
                    accp[1] = ffma2(a.y,  wvp, accp[1]);
                    accp[2] = ffma2(c2.x, wvp, accp[2]);
                    accp[3] = ffma2(c2.y, wvp, accp[3]);
                }
            }
        }
    }

    if (oc < 27) {
        const float bo = b_off[oc];
        float av[8];
#pragma unroll
        for (int j = 0; j < 4; j++) unpack2(accp[j], av[2 * j], av[2 * j + 1]);
#pragma unroll
        for (int j = 0; j < 8; j++) {
            float v = av[j] + bo;
            if (oc >= 18) v = 1.f / (1.f + expf(-v));
            const int px = pg * 8 + j;
            g_om[((size_t)((b * Hh + h) * Ww + w0 + px)) * 27 + oc] = v;
        }
    }
}

// ===================== prep: w_conv -> [chunk][f][k] bf16 hi/lo =============
// chunk = tap*8 + cc covers channels c = cc*32 .. +31 of tap.
__global__ __launch_bounds__(256) void prep_w_kernel(const float* __restrict__ w_conv)
{
    const int g = blockIdx.x * 256 + threadIdx.x;    // 0 .. 294911
    const int kp = g & 15;           // pair of channels within chunk
    const int f  = (g >> 4) & 255;
    const int chunk = g >> 12;       // 0..71
    const int tap = chunk >> 3, cc = chunk & 7;
    const int c = cc * 32 + 2 * kp;
    const float v0 = w_conv[((size_t)(tap * Cc + c)     * Ff) + f];
    const float v1 = w_conv[((size_t)(tap * Cc + c + 1) * Ff) + f];
    const uint32_t hw = cvt_bf16x2(v0, v1);
    const float h0 = __uint_as_float(hw << 16);
    const float h1 = __uint_as_float(hw & 0xffff0000u);
    const uint32_t lw = cvt_bf16x2(v0 - h0, v1 - h1);
    const int o = (chunk * 256 + f) * 16 + kp;
    g_wbh[o] = hw;
    g_wbl[o] = lw;
}

// ===================== Kernel B: mma.sync deformable GEMM ===================
// CTA: 128 px x 128 f. 8 warps: wm = warp>>2 (M 64), wn = warp&3 (N 32).
// smem rows: 40 halves (80B stride) -> conflict-free ldmatrix.
#define OFF_A_HI 0
#define OFF_A_LO 10240
#define OFF_B_HI 20480
#define OFF_B_LO 30720
#define OFF_MW   40960
#define OFF_MI   43008
#define SMEM_SZ  45056

__global__ __launch_bounds__(256, 1) void dcn_mma_kernel(
    const float* __restrict__ x, const float* __restrict__ b_conv,
    float* __restrict__ out)
{
    __shared__ __align__(16) char smem[SMEM_SZ];
    const uint32_t sb = smem_u32(smem);

    const int tid  = threadIdx.x;
    const int warp = tid >> 5;
    const int lane = tid & 31;
    const int wm = warp >> 2;        // 0..1
    const int wn = warp & 3;         // 0..3
    const int p0 = blockIdx.x * 128;
    const int fh = blockIdx.y;       // f half: 0 or 1

    float acc[4][4][4];
#pragma unroll
    for (int mt = 0; mt < 4; mt++)
#pragma unroll
        for (int nt = 0; nt < 4; nt++)
#pragma unroll
            for (int q = 0; q < 4; q++) acc[mt][nt][q] = 0.f;

    // ldmatrix base offsets (halves)
    const uint32_t a_row = (uint32_t)((wm * 64 + (lane & 15)) * 40 + (lane >> 4) * 8);
    const uint32_t b_row = (uint32_t)((wn * 32 + (lane & 7) + ((lane >> 4) << 3)) * 40
                                      + ((lane >> 3) & 1) * 8);

    const int spx   = tid >> 1;      // staging pixel
    const int chalf = tid & 1;       // staging channel half (16 c)

    for (int tap = 0; tap < 9; tap++) {
        // ---- bilinear meta for 128 px ----
        if (tid < 128) {
            const int px = tid;
            const int p = p0 + px;
            const int wpix = p % Ww;
            const int hw_  = p / Ww;
            const int h = hw_ % Hh;
            const int b = hw_ / Hh;
            const float* om = g_om + (size_t)p * 27;
            const float dy = om[tap], dx = om[9 + tap], mask = om[18 + tap];
            const int ky = tap / 3, kx = tap % 3;
            const float ys = (float)(h + ky - 1) + dy;
            const float xs = (float)(wpix + kx - 1) + dx;
            const float y0f = floorf(ys), x0f = floorf(xs);
            const float wy1 = ys - y0f, wx1 = xs - x0f;
            const float wy0 = 1.f - wy1, wx0 = 1.f - wx1;
            const int y0 = (int)y0f, x0i = (int)x0f;
            const int y1 = y0 + 1,   x1i = x0i + 1;
            const bool vy0 = (y0  >= 0) && (y0  < Hh);
            const bool vy1 = (y1  >= 0) && (y1  < Hh);
            const bool vx0 = (x0i >= 0) && (x0i < Ww);
            const bool vx1 = (x1i >= 0) && (x1i < Ww);
            const float c00 = (vy0 && vx0) ? wy0 * wx0 * mask : 0.f;
            const float c01 = (vy0 && vx1) ? wy0 * wx1 * mask : 0.f;
            const float c10 = (vy1 && vx0) ? wy1 * wx0 * mask : 0.f;
            const float c11 = (vy1 && vx1) ? wy1 * wx1 * mask : 0.f;
            const int y0c = min(max(y0, 0), Hh - 1), y1c = min(max(y1, 0), Hh - 1);
            const int x0c = min(max(x0i, 0), Ww - 1), x1c = min(max(x1i, 0), Ww - 1);
            const int r0 = (b * Hh + y0c) * Ww, r1 = (b * Hh + y1c) * Ww;
            *(float4*)(smem + OFF_MW + px * 16) = make_float4(c00, c01, c10, c11);
            *(int4*)(smem + OFF_MI + px * 16) =
                make_int4((r0 + x0c) * Cc, (r0 + x1c) * Cc,
                          (r1 + x0c) * Cc, (r1 + x1c) * Cc);
        }
        __syncthreads();

        const float4 cw = *(const float4*)(smem + OFF_MW + spx * 16);
        const int4   ai = *(const int4*)(smem + OFF_MI + spx * 16);

        for (int cc = 0; cc < 8; cc++) {
            const int chunk = tap * 8 + cc;
            // ---- stage A: gather + bilinear + bf16 split ----
            {
                const int cg = cc * 32 + chalf * 16;
                float v[16];
#pragma unroll
                for (int q = 0; q < 4; q++) {
                    const float4 p00 = *(const float4*)(x + ai.x + cg + 4 * q);
                    const float4 p01 = *(const float4*)(x + ai.y + cg + 4 * q);
                    const float4 p10 = *(const float4*)(x + ai.z + cg + 4 * q);
                    const float4 p11 = *(const float4*)(x + ai.w + cg + 4 * q);
                    v[4*q+0] = cw.x*p00.x + cw.y*p01.x + cw.z*p10.x + cw.w*p11.x;
                    v[4*q+1] = cw.x*p00.y + cw.y*p01.y + cw.z*p10.y + cw.w*p11.y;
                    v[4*q+2] = cw.x*p00.z + cw.y*p01.z + cw.z*p10.z + cw.w*p11.z;
                    v[4*q+3] = cw.x*p00.w + cw.y*p01.w + cw.z*p10.w + cw.w*p11.w;
                }
                const uint32_t sbase = (uint32_t)(spx * 80 + chalf * 32);
#pragma unroll
                for (int q = 0; q < 4; q++) {
                    const uint32_t h0 = cvt_bf16x2(v[4*q+0], v[4*q+1]);
                    const uint32_t h1 = cvt_bf16x2(v[4*q+2], v[4*q+3]);
                    uint2 hp = make_uint2(h0, h1);
                    const float r0 = v[4*q+0] - __uint_as_float(h0 << 16);
                    const float r1 = v[4*q+1] - __uint_as_float(h0 & 0xffff0000u);
                    const float r2 = v[4*q+2] - __uint_as_float(h1 << 16);
                    const float r3 = v[4*q+3] - __uint_as_float(h1 & 0xffff0000u);
                    uint2 lp = make_uint2(cvt_bf16x2(r0, r1), cvt_bf16x2(r2, r3));
                    *(uint2*)(smem + OFF_A_HI + sbase + q * 8) = hp;
                    *(uint2*)(smem + OFF_A_LO + sbase + q * 8) = lp;
                }
            }
            // ---- stage B: copy pre-split weights (128 f x 32 k) ----
            {
                const int row = tid >> 1;
                const int h32 = tid & 1;
                const size_t src = ((size_t)(chunk * 256 + fh * 128 + row) * 16)
                                   + h32 * 8;
                const uint4* sH = (const uint4*)&g_wbh[src];
                const uint4* sL = (const uint4*)&g_wbl[src];
                char* dH = smem + OFF_B_HI + row * 80 + h32 * 32;
                char* dL = smem + OFF_B_LO + row * 80 + h32 * 32;
                ((uint4*)dH)[0] = sH[0]; ((uint4*)dH)[1] = sH[1];
                ((uint4*)dL)[0] = sL[0]; ((uint4*)dL)[1] = sL[1];
            }
            __syncthreads();

            // ---- MMA: 2 k16-steps x (4 mt x 4 nt) x 3 split-terms ----
#pragma unroll
            for (int ks = 0; ks < 2; ks++) {
                uint32_t aH[4][4], aL[4][4];
#pragma unroll
                for (int mt = 0; mt < 4; mt++) {
                    const uint32_t ao = (a_row + mt * 640 + ks * 16) * 2;
                    ldsm4(aH[mt], sb + OFF_A_HI + ao);
                    ldsm4(aL[mt], sb + OFF_A_LO + ao);
                }
                uint32_t bH[2][4], bL[2][4];
#pragma unroll
                for (int np = 0; np < 2; np++) {
                    const uint32_t bo = (b_row + np * 640 + ks * 16) * 2;
                    ldsm4(bH[np], sb + OFF_B_HI + bo);
                    ldsm4(bL[np], sb + OFF_B_LO + bo);
                }
#pragma unroll
                for (int mt = 0; mt < 4; mt++) {
#pragma unroll
                    for (int nt = 0; nt < 4; nt++) {
                        const int np = nt >> 1, s = (nt & 1) * 2;
                        mma_bf16(acc[mt][nt], aH[mt], bH[np][s], bH[np][s + 1]);
                        mma_bf16(acc[mt][nt], aL[mt], bH[np][s], bH[np][s + 1]);
                        mma_bf16(acc[mt][nt], aH[mt], bL[np][s], bL[np][s + 1]);
                    }
                }
            }
            __syncthreads();
        }
    }

    // ---- epilogue: + bias, store ----
    const int gid = lane >> 2, tig = lane & 3;
#pragma unroll
    for (int mt = 0; mt < 4; mt++) {
        const int row0 = p0 + wm * 64 + mt * 16 + gid;
#pragma unroll
        for (int nt = 0; nt < 4; nt++) {
            const int f0 = fh * 128 + wn * 32 + nt * 8 + 2 * tig;
            const float2 bcv = *(const float2*)(b_conv + f0);
            float2 o0, o1;
            o0.x = acc[mt][nt][0] + bcv.x;
            o0.y = acc[mt][nt][1] + bcv.y;
            o1.x = acc[mt][nt][2] + bcv.x;
            o1.y = acc[mt][nt][3] + bcv.y;
            *(float2*)(out + (size_t)row0 * Ff + f0) = o0;
            *(float2*)(out + (size_t)(row0 + 8) * Ff + f0) = o1;
        }
    }
}

// ===================== launch ==============================================
extern "C" void kernel_launch(void* const* d_in, const int* in_sizes, int n_in,
                              void* d_out, int out_size)
{
    (void)in_sizes; (void)n_in; (void)out_size;
    const float* x      = (const float*)d_in[0];
    const float* w_off  = (const float*)d_in[1];
    const float* b_off  = (const float*)d_in[2];
    const float* w_conv = (const float*)d_in[3];
    const float* b_conv = (const float*)d_in[4];
    float* out = (float*)d_out;

    prep_w_kernel<<<1152, 256>>>(w_conv);
    dim3 gA(3, 96, 4);
    offset_conv_kernel<<<gA, 128>>>(x, w_off, b_off);
    dim3 gB(288, 2);
    dcn_mma_kernel<<<gB, 256>>>(x, b_conv, out);
}

// round 6
// speedup vs baseline: 1.7632x; 1.2150x over previous
#include <cuda_runtime.h>
#include <cuda_bf16.h>
#include <math.h>
#include <stdint.h>

#define Bb 4
#define Hh 96
#define Ww 96
#define Cc 256
#define Ff 256

typedef unsigned long long u64;

// ===================== scalar helpers (kernel A) ============================
__device__ __forceinline__ u64 ffma2(u64 a, u64 b, u64 c) {
    u64 d;
    asm("fma.rn.f32x2 %0, %1, %2, %3;" : "=l"(d) : "l"(a), "l"(b), "l"(c));
    return d;
}
__device__ __forceinline__ u64 pack2(float lo, float hi) {
    u64 d;
    asm("mov.b64 %0, {%1, %2};" : "=l"(d) : "f"(lo), "f"(hi));
    return d;
}
__device__ __forceinline__ void unpack2(u64 v, float& lo, float& hi) {
    asm("mov.b64 {%0, %1}, %2;" : "=f"(lo), "=f"(hi) : "l"(v));
}

// ===================== mma.sync helpers =====================================
__device__ __forceinline__ uint32_t smem_u32(const void* p) {
    uint32_t a;
    asm("{ .reg .u64 t; cvta.to.shared.u64 t, %1; cvt.u32.u64 %0, t; }"
        : "=r"(a) : "l"(p));
    return a;
}
__device__ __forceinline__ void ldsm4(uint32_t* r, uint32_t addr) {
    asm volatile("ldmatrix.sync.aligned.m8n8.x4.shared.b16 {%0,%1,%2,%3}, [%4];"
        : "=r"(r[0]), "=r"(r[1]), "=r"(r[2]), "=r"(r[3]) : "r"(addr));
}
__device__ __forceinline__ void mma_bf16(float* d, const uint32_t* a,
                                         uint32_t b0, uint32_t b1) {
    asm volatile(
        "mma.sync.aligned.m16n8k16.row.col.f32.bf16.bf16.f32 "
        "{%0,%1,%2,%3}, {%4,%5,%6,%7}, {%8,%9}, {%0,%1,%2,%3};"
        : "+f"(d[0]), "+f"(d[1]), "+f"(d[2]), "+f"(d[3])
        : "r"(a[0]), "r"(a[1]), "r"(a[2]), "r"(a[3]), "r"(b0), "r"(b1));
}
__device__ __forceinline__ uint32_t cvt_bf16x2(float v0, float v1) {
    uint32_t d;
    asm("cvt.rn.bf16x2.f32 %0, %1, %2;" : "=r"(d) : "f"(v1), "f"(v0));
    return d;
}
__device__ __forceinline__ void cp16(uint32_t dst, const void* src) {
    asm volatile("cp.async.cg.shared.global [%0], [%1], 16;"
                 :: "r"(dst), "l"(src));
}
#define CP_COMMIT() asm volatile("cp.async.commit_group;" ::: "memory")
#define CP_WAIT0()  asm volatile("cp.async.wait_group 0;" ::: "memory")

// ===================== device scratch =======================================
__device__ float g_om[Bb * Hh * Ww * 27];          // dy[9], dx[9], sig(mask)[9]
// w_conv, bf16-split, layout [chunk=72][f=256][16 x bf16x2 along k]
__device__ uint32_t g_wbh[72 * 256 * 16];
__device__ uint32_t g_wbl[72 * 256 * 16];

// ===================== Kernel A: offset conv ================================
__global__ __launch_bounds__(128) void offset_conv_kernel(
    const float* __restrict__ x, const float* __restrict__ w_off,
    const float* __restrict__ b_off)
{
    __shared__ __align__(16) float xs_s[16][36];
    __shared__ float ws_s[16][28];

    const int w0 = blockIdx.x * 32;
    const int h  = blockIdx.y;
    const int b  = blockIdx.z;
    const int tid = threadIdx.x;
    const int oc = tid & 31;
    const int pg = tid >> 5;

    u64 accp[4];
#pragma unroll
    for (int j = 0; j < 4; j++) accp[j] = 0ULL;

    for (int t = 0; t < 9; t++) {
        const int ky = t / 3, kx = t % 3;
        const int y = h + ky - 1;
        if (y < 0 || y >= Hh) continue;
        const float* xrow = x + ((size_t)(b * Hh + y) * Ww) * Cc;

        for (int cc = 0; cc < 16; cc++) {
            __syncthreads();
            {
                const int ci  = tid & 15;
                const int pxg = tid >> 4;
#pragma unroll
                for (int j = 0; j < 4; j++) {
                    const int px = pxg + j * 8;
                    const int xc = w0 + px + kx - 1;
                    float v = 0.f;
                    if (xc >= 0 && xc < Ww) v = xrow[xc * Cc + cc * 16 + ci];
                    xs_s[ci][px] = v;
                }
            }
            for (int idx = tid; idx < 16 * 27; idx += 128) {
                const int ci = idx / 27, o = idx % 27;
                ws_s[ci][o] = w_off[(t * Cc + cc * 16 + ci) * 27 + o];
            }
            __syncthreads();

            if (oc < 27) {
#pragma unroll
                for (int ci = 0; ci < 16; ci++) {
                    const float wv = ws_s[ci][oc];
                    const u64 wvp = pack2(wv, wv);
                    const float* xr = &xs_s[ci][pg * 8];
                    const ulonglong2 a  = *(const ulonglong2*)(xr);
                    const ulonglong2 c2 = *(const ulonglong2*)(xr + 4);
                    accp[0] = ffma2(a.x,  wvp, accp[0]);
                    accp[1] = ffma2(a.y,  wvp, accp[1]);
                    accp[2] = ffma2(c2.x, wvp, accp[2]);
                    accp[3] = ffma2(c2.y, wvp, accp[3]);
                }
            }
        }
    }

    if (oc < 27) {
        const float bo = b_off[oc];
        float av[8];
#pragma unroll
        for (int j = 0; j < 4; j++) unpack2(accp[j], av[2 * j], av[2 * j + 1]);
#pragma unroll
        for (int j = 0; j < 8; j++) {
            float v = av[j] + bo;
            if (oc >= 18) v = 1.f / (1.f + expf(-v));
            const int px = pg * 8 + j;
            g_om[((size_t)((b * Hh + h) * Ww + w0 + px)) * 27 + oc] = v;
        }
    }
}

// ===================== prep: w_conv -> [chunk][f][k] bf16 hi/lo =============
__global__ __launch_bounds__(256) void prep_w_kernel(const float* __restrict__ w_conv)
{
    const int g = blockIdx.x * 256 + threadIdx.x;    // 0 .. 294911
    const int kp = g & 15;
    const int f  = (g >> 4) & 255;
    const int chunk = g >> 12;       // 0..71
    const int tap = chunk >> 3, cc = chunk & 7;
    const int c = cc * 32 + 2 * kp;
    const float v0 = w_conv[((size_t)(tap * Cc + c)     * Ff) + f];
    const float v1 = w_conv[((size_t)(tap * Cc + c + 1) * Ff) + f];
    const uint32_t hw = cvt_bf16x2(v0, v1);
    const float h0 = __uint_as_float(hw << 16);
    const float h1 = __uint_as_float(hw & 0xffff0000u);
    const uint32_t lw = cvt_bf16x2(v0 - h0, v1 - h1);
    const int o = (chunk * 256 + f) * 16 + kp;
    g_wbh[o] = hw;
    g_wbl[o] = lw;
}

// ===================== Kernel B: pipelined mma.sync deformable GEMM =========
// CTA: 128 px x 128 f; double-buffered smem; 1 barrier/chunk; cp.async for B.
#define BUF_SZ   40960        // per-buffer: A_HI|A_LO|B_HI|B_LO, 10240 each
#define OFF_A_HI 0
#define OFF_A_LO 10240
#define OFF_B_HI 20480
#define OFF_B_LO 30720
#define OFF_META 81920        // MW0|MI0|MW1|MI1, 2048 each
#define SMEM_SZ  90112

__device__ __forceinline__ void compute_meta(char* smem, int p0, int px,
                                             int tap, int mbuf) {
    const int p = p0 + px;
    const int wpix = p % Ww;
    const int hw_  = p / Ww;
    const int h = hw_ % Hh;
    const int b = hw_ / Hh;
    const float* om = g_om + (size_t)p * 27;
    const float dy = om[tap], dx = om[9 + tap], mask = om[18 + tap];
    const int ky = tap / 3, kx = tap % 3;
    const float ys = (float)(h + ky - 1) + dy;
    const float xs = (float)(wpix + kx - 1) + dx;
    const float y0f = floorf(ys), x0f = floorf(xs);
    const float wy1 = ys - y0f, wx1 = xs - x0f;
    const float wy0 = 1.f - wy1, wx0 = 1.f - wx1;
    const int y0 = (int)y0f, x0i = (int)x0f;
    const int y1 = y0 + 1,   x1i = x0i + 1;
    const bool vy0 = (y0  >= 0) && (y0  < Hh);
    const bool vy1 = (y1  >= 0) && (y1  < Hh);
    const bool vx0 = (x0i >= 0) && (x0i < Ww);
    const bool vx1 = (x1i >= 0) && (x1i < Ww);
    const float c00 = (vy0 && vx0) ? wy0 * wx0 * mask : 0.f;
    const float c01 = (vy0 && vx1) ? wy0 * wx1 * mask : 0.f;
    const float c10 = (vy1 && vx0) ? wy1 * wx0 * mask : 0.f;
    const float c11 = (vy1 && vx1) ? wy1 * wx1 * mask : 0.f;
    const int y0c = min(max(y0, 0), Hh - 1), y1c = min(max(y1, 0), Hh - 1);
    const int x0c = min(max(x0i, 0), Ww - 1), x1c = min(max(x1i, 0), Ww - 1);
    const int r0 = (b * Hh + y0c) * Ww, r1 = (b * Hh + y1c) * Ww;
    char* mb = smem + OFF_META + mbuf * 4096;
    *(float4*)(mb + px * 16) = make_float4(c00, c01, c10, c11);
    *(int4*)(mb + 2048 + px * 16) =
        make_int4((r0 + x0c) * Cc, (r0 + x1c) * Cc,
                  (r1 + x0c) * Cc, (r1 + x1c) * Cc);
}

__global__ __launch_bounds__(256, 2) void dcn_mma_kernel(
    const float* __restrict__ x, const float* __restrict__ b_conv,
    float* __restrict__ out)
{
    extern __shared__ __align__(16) char smem[];
    const uint32_t sb = smem_u32(smem);

    const int tid  = threadIdx.x;
    const int warp = tid >> 5;
    const int lane = tid & 31;
    const int wm = warp >> 2;        // 0..1
    const int wn = warp & 3;         // 0..3
    const int p0 = blockIdx.x * 128;
    const int fh = blockIdx.y;       // f half: 0 or 1

    float acc[4][4][4];
#pragma unroll
    for (int mt = 0; mt < 4; mt++)
#pragma unroll
        for (int nt = 0; nt < 4; nt++)
#pragma unroll
            for (int q = 0; q < 4; q++) acc[mt][nt][q] = 0.f;

    // ldmatrix base offsets (in halves)
    const uint32_t a_row = (uint32_t)((wm * 64 + (lane & 15)) * 40 + (lane >> 4) * 8);
    const uint32_t b_row = (uint32_t)((wn * 32 + (lane & 7) + ((lane >> 4) << 3)) * 40
                                      + ((lane >> 3) & 1) * 8);

    const int spx   = tid >> 1;      // staging pixel
    const int chalf = tid & 1;       // staging channel half (16 c)
    const int brow  = tid >> 1;      // B staging row
    const int bh32  = tid & 1;

    // ---- staging for chunk i into buffer (i&1) ----
    auto stage = [&](int i) {
        const int tap = i >> 3, cc = i & 7;
        const int bi = i & 1;
        char* buf = smem + bi * BUF_SZ;
        const char* mb = smem + OFF_META + (tap & 1) * 4096;
        const float4 cw = *(const float4*)(mb + spx * 16);
        const int4   ai = *(const int4*)(mb + 2048 + spx * 16);
        // A: gather + bilinear + bf16 split
        const int cg = cc * 32 + chalf * 16;
        float v[16];
#pragma unroll
        for (int q = 0; q < 4; q++) {
            const float4 p00 = *(const float4*)(x + ai.x + cg + 4 * q);
            const float4 p01 = *(const float4*)(x + ai.y + cg + 4 * q);
            const float4 p10 = *(const float4*)(x + ai.z + cg + 4 * q);
            const float4 p11 = *(const float4*)(x + ai.w + cg + 4 * q);
            v[4*q+0] = cw.x*p00.x + cw.y*p01.x + cw.z*p10.x + cw.w*p11.x;
            v[4*q+1] = cw.x*p00.y + cw.y*p01.y + cw.z*p10.y + cw.w*p11.y;
            v[4*q+2] = cw.x*p00.z + cw.y*p01.z + cw.z*p10.z + cw.w*p11.z;
            v[4*q+3] = cw.x*p00.w + cw.y*p01.w + cw.z*p10.w + cw.w*p11.w;
        }
        const uint32_t sbase = (uint32_t)(spx * 80 + chalf * 32);
#pragma unroll
        for (int q = 0; q < 4; q++) {
            const uint32_t h0 = cvt_bf16x2(v[4*q+0], v[4*q+1]);
            const uint32_t h1 = cvt_bf16x2(v[4*q+2], v[4*q+3]);
            const float r0 = v[4*q+0] - __uint_as_float(h0 << 16);
            const float r1 = v[4*q+1] - __uint_as_float(h0 & 0xffff0000u);
            const float r2 = v[4*q+2] - __uint_as_float(h1 << 16);
            const float r3 = v[4*q+3] - __uint_as_float(h1 & 0xffff0000u);
            *(uint2*)(buf + OFF_A_HI + sbase + q * 8) = make_uint2(h0, h1);
            *(uint2*)(buf + OFF_A_LO + sbase + q * 8) =
                make_uint2(cvt_bf16x2(r0, r1), cvt_bf16x2(r2, r3));
        }
        // B: cp.async pre-split weights (128 f x 32 k)
        const size_t src = ((size_t)(i * 256 + fh * 128 + brow) * 16) + bh32 * 8;
        const uint32_t dH = sb + bi * BUF_SZ + OFF_B_HI + brow * 80 + bh32 * 32;
        const uint32_t dL = sb + bi * BUF_SZ + OFF_B_LO + brow * 80 + bh32 * 32;
        cp16(dH,      &g_wbh[src]);
        cp16(dH + 16, &g_wbh[src + 4]);
        cp16(dL,      &g_wbl[src]);
        cp16(dL + 16, &g_wbl[src + 4]);
        CP_COMMIT();
    };

    // ---- prologue ----
    if (tid < 128) compute_meta(smem, p0, tid, 0, 0);
    __syncthreads();
    stage(0);

    for (int i = 0; i < 72; i++) {
        CP_WAIT0();
        __syncthreads();
        if (i < 71) stage(i + 1);
        // meta for next tap, one iteration before first use
        if ((i & 7) == 6 && i < 64) {
            const int ntap = (i >> 3) + 1;
            if (tid < 128) compute_meta(smem, p0, tid, ntap, ntap & 1);
        }
        // ---- MMA burst for chunk i ----
        const uint32_t bufb = sb + (i & 1) * BUF_SZ;
#pragma unroll
        for (int ks = 0; ks < 2; ks++) {
            uint32_t bH[2][4], bL[2][4];
#pragma unroll
            for (int np = 0; np < 2; np++) {
                const uint32_t bo = (b_row + np * 640 + ks * 16) * 2;
                ldsm4(bH[np], bufb + OFF_B_HI + bo);
                ldsm4(bL[np], bufb + OFF_B_LO + bo);
            }
#pragma unroll
            for (int mt = 0; mt < 4; mt++) {
                uint32_t aH[4], aL[4];
                const uint32_t ao = (a_row + mt * 640 + ks * 16) * 2;
                ldsm4(aH, bufb + OFF_A_HI + ao);
                ldsm4(aL, bufb + OFF_A_LO + ao);
#pragma unroll
                for (int nt = 0; nt < 4; nt++) {
                    const int np = nt >> 1, s = (nt & 1) * 2;
                    mma_bf16(acc[mt][nt], aH, bH[np][s], bH[np][s + 1]);
                    mma_bf16(acc[mt][nt], aL, bH[np][s], bH[np][s + 1]);
                    mma_bf16(acc[mt][nt], aH, bL[np][s], bL[np][s + 1]);
                }
            }
        }
    }

    // ---- epilogue: + bias, store ----
    const int gid = lane >> 2, tig = lane & 3;
#pragma unroll
    for (int mt = 0; mt < 4; mt++) {
        const int row0 = p0 + wm * 64 + mt * 16 + gid;
#pragma unroll
        for (int nt = 0; nt < 4; nt++) {
            const int f0 = fh * 128 + wn * 32 + nt * 8 + 2 * tig;
            const float2 bcv = *(const float2*)(b_conv + f0);
            float2 o0, o1;
            o0.x = acc[mt][nt][0] + bcv.x;
            o0.y = acc[mt][nt][1] + bcv.y;
            o1.x = acc[mt][nt][2] + bcv.x;
            o1.y = acc[mt][nt][3] + bcv.y;
            *(float2*)(out + (size_t)row0 * Ff + f0) = o0;
            *(float2*)(out + (size_t)(row0 + 8) * Ff + f0) = o1;
        }
    }
}

// ===================== launch ==============================================
extern "C" void kernel_launch(void* const* d_in, const int* in_sizes, int n_in,
                              void* d_out, int out_size)
{
    (void)in_sizes; (void)n_in; (void)out_size;
    const float* x      = (const float*)d_in[0];
    const float* w_off  = (const float*)d_in[1];
    const float* b_off  = (const float*)d_in[2];
    const float* w_conv = (const float*)d_in[3];
    const float* b_conv = (const float*)d_in[4];
    float* out = (float*)d_out;

    cudaFuncSetAttribute(dcn_mma_kernel,
                         cudaFuncAttributeMaxDynamicSharedMemorySize, SMEM_SZ);

    prep_w_kernel<<<1152, 256>>>(w_conv);
    dim3 gA(3, 96, 4);
    offset_conv_kernel<<<gA, 128>>>(x, w_off, b_off);
    dim3 gB(288, 2);
    dcn_mma_kernel<<<gB, 256, SMEM_SZ>>>(x, b_conv, out);
}

// round 7
// speedup vs baseline: 2.5996x; 1.4743x over previous
#include <cuda_runtime.h>
#include <cuda_bf16.h>
#include <math.h>
#include <stdint.h>

#define Bb 4
#define Hh 96
#define Ww 96
#define Cc 256
#define Ff 256

typedef unsigned long long u64;

// ===================== mma.sync helpers =====================================
__device__ __forceinline__ uint32_t smem_u32(const void* p) {
    uint32_t a;
    asm("{ .reg .u64 t; cvta.to.shared.u64 t, %1; cvt.u32.u64 %0, t; }"
        : "=r"(a) : "l"(p));
    return a;
}
__device__ __forceinline__ void ldsm4(uint32_t* r, uint32_t addr) {
    asm volatile("ldmatrix.sync.aligned.m8n8.x4.shared.b16 {%0,%1,%2,%3}, [%4];"
        : "=r"(r[0]), "=r"(r[1]), "=r"(r[2]), "=r"(r[3]) : "r"(addr));
}
__device__ __forceinline__ void mma_bf16(float* d, const uint32_t* a,
                                         uint32_t b0, uint32_t b1) {
    asm volatile(
        "mma.sync.aligned.m16n8k16.row.col.f32.bf16.bf16.f32 "
        "{%0,%1,%2,%3}, {%4,%5,%6,%7}, {%8,%9}, {%0,%1,%2,%3};"
        : "+f"(d[0]), "+f"(d[1]), "+f"(d[2]), "+f"(d[3])
        : "r"(a[0]), "r"(a[1]), "r"(a[2]), "r"(a[3]), "r"(b0), "r"(b1));
}
__device__ __forceinline__ uint32_t cvt_bf16x2(float v0, float v1) {
    uint32_t d;
    asm("cvt.rn.bf16x2.f32 %0, %1, %2;" : "=r"(d) : "f"(v1), "f"(v0));
    return d;
}
__device__ __forceinline__ void cp16(uint32_t dst, const void* src) {
    asm volatile("cp.async.cg.shared.global [%0], [%1], 16;"
                 :: "r"(dst), "l"(src));
}
// zero-fill variant: src_size=0 -> dst gets zeros
__device__ __forceinline__ void cp16z(uint32_t dst, const void* src, int sz) {
    asm volatile("cp.async.cg.shared.global [%0], [%1], 16, %2;"
                 :: "r"(dst), "l"(src), "r"(sz));
}
#define CP_COMMIT() asm volatile("cp.async.commit_group;" ::: "memory")
#define CP_WAIT0()  asm volatile("cp.async.wait_group 0;" ::: "memory")

// ===================== device scratch =======================================
__device__ float g_om[Bb * Hh * Ww * 27];          // dy[9], dx[9], sig(mask)[9]
// w_conv, bf16-split, layout [chunk=72][f=256][16 x bf16x2 along k]
__device__ uint32_t g_wbh[72 * 256 * 16];
__device__ uint32_t g_wbl[72 * 256 * 16];
// w_off, bf16-split, layout [chunk=72][f=32 (27 used)][16 x bf16x2]
__device__ uint32_t g_wobh[72 * 32 * 16];
__device__ uint32_t g_wobl[72 * 32 * 16];
// x, bf16-split, as bf16x2 words: [B*H*W*C/2]
#define XWORDS (Bb * Hh * Ww * Cc / 2)
__device__ uint32_t g_xh[XWORDS];
__device__ uint32_t g_xl[XWORDS];

// ===================== prep kernels =========================================
__global__ __launch_bounds__(256) void prep_w_kernel(const float* __restrict__ w_conv)
{
    const int g = blockIdx.x * 256 + threadIdx.x;    // 0 .. 294911
    const int kp = g & 15;
    const int f  = (g >> 4) & 255;
    const int chunk = g >> 12;       // 0..71
    const int tap = chunk >> 3, cc = chunk & 7;
    const int c = cc * 32 + 2 * kp;
    const float v0 = w_conv[((size_t)(tap * Cc + c)     * Ff) + f];
    const float v1 = w_conv[((size_t)(tap * Cc + c + 1) * Ff) + f];
    const uint32_t hw = cvt_bf16x2(v0, v1);
    const float h0 = __uint_as_float(hw << 16);
    const float h1 = __uint_as_float(hw & 0xffff0000u);
    const uint32_t lw = cvt_bf16x2(v0 - h0, v1 - h1);
    const int o = (chunk * 256 + f) * 16 + kp;
    g_wbh[o] = hw;
    g_wbl[o] = lw;
}

__global__ __launch_bounds__(256) void prep_woff_kernel(const float* __restrict__ w_off)
{
    const int g = blockIdx.x * 256 + threadIdx.x;    // 0 .. 36863
    const int kp = g & 15;
    const int f  = (g >> 4) & 31;
    const int chunk = g >> 9;        // 0..71
    const int tap = chunk >> 3, cc = chunk & 7;
    const int c = cc * 32 + 2 * kp;
    float v0 = 0.f, v1 = 0.f;
    if (f < 27) {
        v0 = w_off[((size_t)(tap * Cc + c)     * 27) + f];
        v1 = w_off[((size_t)(tap * Cc + c + 1) * 27) + f];
    }
    const uint32_t hw = cvt_bf16x2(v0, v1);
    const float h0 = __uint_as_float(hw << 16);
    const float h1 = __uint_as_float(hw & 0xffff0000u);
    const uint32_t lw = cvt_bf16x2(v0 - h0, v1 - h1);
    const int o = (chunk * 32 + f) * 16 + kp;
    g_wobh[o] = hw;
    g_wobl[o] = lw;
}

__global__ __launch_bounds__(256) void prep_x_kernel(const float* __restrict__ x)
{
    const int i = blockIdx.x * 256 + threadIdx.x;    // 0 .. XWORDS-1
    const float2 v = ((const float2*)x)[i];
    const uint32_t hw = cvt_bf16x2(v.x, v.y);
    const float h0 = __uint_as_float(hw << 16);
    const float h1 = __uint_as_float(hw & 0xffff0000u);
    const uint32_t lw = cvt_bf16x2(v.x - h0, v.y - h1);
    g_xh[i] = hw;
    g_xl[i] = lw;
}

// ===================== Kernel A: offset conv via mma.sync ===================
// CTA: 128 px x 32 f (27 used); 8 warps, each 16 px x 32 f. Double-buffered.
#define OB_A_HI 0
#define OB_A_LO 10240
#define OB_B_HI 20480
#define OB_B_LO 23040
#define OB_BUF  25600
#define OB_SMEM (2 * OB_BUF)     // 51200

__global__ __launch_bounds__(256) void offset_mma_kernel(
    const float* __restrict__ b_off)
{
    extern __shared__ __align__(16) char smem[];
    const uint32_t sb = smem_u32(smem);
    const int tid  = threadIdx.x;
    const int warp = tid >> 5;
    const int lane = tid & 31;
    const int p0 = blockIdx.x * 128;

    float acc[4][4];
#pragma unroll
    for (int nt = 0; nt < 4; nt++)
#pragma unroll
        for (int q = 0; q < 4; q++) acc[nt][q] = 0.f;

    // fixed per-thread staging pixel
    const int spx = tid >> 1;
    const int h16 = tid & 1;
    const int p = p0 + spx;
    const int wpix = p % Ww;
    const int hw_  = p / Ww;
    const int hh = hw_ % Hh;
    const int bimg = hw_ / Hh;

    const uint32_t a_row = (uint32_t)((warp * 16 + (lane & 15)) * 40 + (lane >> 4) * 8);
    const uint32_t b_row = (uint32_t)(((lane & 7) + ((lane >> 4) << 3)) * 40
                                      + ((lane >> 3) & 1) * 8);

    auto stage = [&](int i) {
        const int tap = i >> 3, cc = i & 7;
        const uint32_t bufb = sb + (i & 1) * OB_BUF;
        const int ky = tap / 3, kx = tap % 3;
        const int y  = hh + ky - 1;
        const int xw = wpix + kx - 1;
        const bool valid = (y >= 0) && (y < Hh) && (xw >= 0) && (xw < Ww);
        const int yc = valid ? y : 0, xc = valid ? xw : 0;
        const size_t srcw = ((((size_t)(bimg * Hh + yc) * Ww + xc) * Cc)
                             + cc * 32 + h16 * 16) >> 1;
        const int sz = valid ? 16 : 0;
        const uint32_t dA = bufb + OB_A_HI + spx * 80 + h16 * 32;
        const uint32_t dL = bufb + OB_A_LO + spx * 80 + h16 * 32;
        cp16z(dA,      &g_xh[srcw],     sz);
        cp16z(dA + 16, &g_xh[srcw + 4], sz);
        cp16z(dL,      &g_xl[srcw],     sz);
        cp16z(dL + 16, &g_xl[srcw + 4], sz);
        if (tid < 64) {
            const int row = tid >> 1, bh = tid & 1;
            const size_t s2 = ((size_t)(i * 32 + row) * 16) + bh * 8;
            const uint32_t dbh = bufb + OB_B_HI + row * 80 + bh * 32;
            const uint32_t dbl = bufb + OB_B_LO + row * 80 + bh * 32;
            cp16(dbh,      &g_wobh[s2]);
            cp16(dbh + 16, &g_wobh[s2 + 4]);
            cp16(dbl,      &g_wobl[s2]);
            cp16(dbl + 16, &g_wobl[s2 + 4]);
        }
        CP_COMMIT();
    };

    stage(0);
    for (int i = 0; i < 72; i++) {
        CP_WAIT0();
        __syncthreads();
        if (i < 71) stage(i + 1);
        const uint32_t bufb = sb + (i & 1) * OB_BUF;
#pragma unroll
        for (int ks = 0; ks < 2; ks++) {
            uint32_t aH[4], aL[4], bH[2][4], bL[2][4];
            ldsm4(aH, bufb + OB_A_HI + (a_row + ks * 16) * 2);
            ldsm4(aL, bufb + OB_A_LO + (a_row + ks * 16) * 2);
#pragma unroll
            for (int np = 0; np < 2; np++) {
                const uint32_t bo = (b_row + np * 640 + ks * 16) * 2;
                ldsm4(bH[np], bufb + OB_B_HI + bo);
                ldsm4(bL[np], bufb + OB_B_LO + bo);
            }
#pragma unroll
            for (int nt = 0; nt < 4; nt++) {
                const int np = nt >> 1, s = (nt & 1) * 2;
                mma_bf16(acc[nt], aH, bH[np][s], bH[np][s + 1]);
                mma_bf16(acc[nt], aL, bH[np][s], bH[np][s + 1]);
                mma_bf16(acc[nt], aH, bL[np][s], bL[np][s + 1]);
            }
        }
    }

    // epilogue: bias + sigmoid(mask) -> g_om
    const int gid = lane >> 2, tig = lane & 3;
    const int row0 = p0 + warp * 16 + gid;
#pragma unroll
    for (int nt = 0; nt < 4; nt++) {
        const int col = nt * 8 + 2 * tig;
#pragma unroll
        for (int e = 0; e < 2; e++) {
            const int c = col + e;
            if (c < 27) {
                const float bo = b_off[c];
                float v0 = acc[nt][e] + bo;
                float v1 = acc[nt][2 + e] + bo;
                if (c >= 18) {
                    v0 = 1.f / (1.f + expf(-v0));
                    v1 = 1.f / (1.f + expf(-v1));
                }
                g_om[(size_t)row0 * 27 + c] = v0;
                g_om[(size_t)(row0 + 8) * 27 + c] = v1;
            }
        }
    }
}

// ===================== Kernel B: pipelined mma.sync deformable GEMM =========
// CTA: 128 px x 256 f (merged halves); double-buffered; 1 barrier/chunk.
#define BUF_SZ   61440        // A_HI|A_LO (10240 each) | B_HI|B_LO (20480 each)
#define OFF_A_HI 0
#define OFF_A_LO 10240
#define OFF_B_HI 20480
#define OFF_B_LO 40960
#define OFF_META 122880       // 2 x (MW 2048 | MI 2048)
#define SMEM_SZ  131072

__device__ __forceinline__ void compute_meta(char* smem, int p0, int px,
                                             int tap, int mbuf) {
    const int p = p0 + px;
    const int wpix = p % Ww;
    const int hw_  = p / Ww;
    const int h = hw_ % Hh;
    const int b = hw_ / Hh;
    const float* om = g_om + (size_t)p * 27;
    const float dy = om[tap], dx = om[9 + tap], mask = om[18 + tap];
    const int ky = tap / 3, kx = tap % 3;
    const float ys = (float)(h + ky - 1) + dy;
    const float xs = (float)(wpix + kx - 1) + dx;
    const float y0f = floorf(ys), x0f = floorf(xs);
    const float wy1 = ys - y0f, wx1 = xs - x0f;
    const float wy0 = 1.f - wy1, wx0 = 1.f - wx1;
    const int y0 = (int)y0f, x0i = (int)x0f;
    const int y1 = y0 + 1,   x1i = x0i + 1;
    const bool vy0 = (y0  >= 0) && (y0  < Hh);
    const bool vy1 = (y1  >= 0) && (y1  < Hh);
    const bool vx0 = (x0i >= 0) && (x0i < Ww);
    const bool vx1 = (x1i >= 0) && (x1i < Ww);
    const float c00 = (vy0 && vx0) ? wy0 * wx0 * mask : 0.f;
    const float c01 = (vy0 && vx1) ? wy0 * wx1 * mask : 0.f;
    const float c10 = (vy1 && vx0) ? wy1 * wx0 * mask : 0.f;
    const float c11 = (vy1 && vx1) ? wy1 * wx1 * mask : 0.f;
    const int y0c = min(max(y0, 0), Hh - 1), y1c = min(max(y1, 0), Hh - 1);
    const int x0c = min(max(x0i, 0), Ww - 1), x1c = min(max(x1i, 0), Ww - 1);
    const int r0 = (b * Hh + y0c) * Ww, r1 = (b * Hh + y1c) * Ww;
    char* mb = smem + OFF_META + mbuf * 4096;
    *(float4*)(mb + px * 16) = make_float4(c00, c01, c10, c11);
    *(int4*)(mb + 2048 + px * 16) =
        make_int4((r0 + x0c) * Cc, (r0 + x1c) * Cc,
                  (r1 + x0c) * Cc, (r1 + x1c) * Cc);
}

__global__ __launch_bounds__(256, 1) void dcn_mma_kernel(
    const float* __restrict__ x, const float* __restrict__ b_conv,
    float* __restrict__ out)
{
    extern __shared__ __align__(16) char smem[];
    const uint32_t sb = smem_u32(smem);

    const int tid  = threadIdx.x;
    const int warp = tid >> 5;
    const int lane = tid & 31;
    const int wm = warp >> 2;        // 0..1 (M 64)
    const int wn = warp & 3;         // 0..3 (N 64)
    const int p0 = blockIdx.x * 128;

    float acc[4][8][4];
#pragma unroll
    for (int mt = 0; mt < 4; mt++)
#pragma unroll
        for (int nt = 0; nt < 8; nt++)
#pragma unroll
            for (int q = 0; q < 4; q++) acc[mt][nt][q] = 0.f;

    const uint32_t a_row = (uint32_t)((wm * 64 + (lane & 15)) * 40 + (lane >> 4) * 8);
    const uint32_t b_row = (uint32_t)((wn * 64 + (lane & 7) + ((lane >> 4) << 3)) * 40
                                      + ((lane >> 3) & 1) * 8);

    const int spx   = tid >> 1;      // staging pixel
    const int chalf = tid & 1;       // staging channel half (16 c)

    auto stage = [&](int i) {
        const int tap = i >> 3, cc = i & 7;
        const int bi = i & 1;
        char* buf = smem + bi * BUF_SZ;
        const char* mb = smem + OFF_META + (tap & 1) * 4096;
        const float4 cw = *(const float4*)(mb + spx * 16);
        const int4   ai = *(const int4*)(mb + 2048 + spx * 16);
        // A: gather + bilinear + bf16 split
        const int cg = cc * 32 + chalf * 16;
        float v[16];
#pragma unroll
        for (int q = 0; q < 4; q++) {
            const float4 p00 = *(const float4*)(x + ai.x + cg + 4 * q);
            const float4 p01 = *(const float4*)(x + ai.y + cg + 4 * q);
            const float4 p10 = *(const float4*)(x + ai.z + cg + 4 * q);
            const float4 p11 = *(const float4*)(x + ai.w + cg + 4 * q);
            v[4*q+0] = cw.x*p00.x + cw.y*p01.x + cw.z*p10.x + cw.w*p11.x;
            v[4*q+1] = cw.x*p00.y + cw.y*p01.y + cw.z*p10.y + cw.w*p11.y;
            v[4*q+2] = cw.x*p00.z + cw.y*p01.z + cw.z*p10.z + cw.w*p11.z;
            v[4*q+3] = cw.x*p00.w + cw.y*p01.w + cw.z*p10.w + cw.w*p11.w;
        }
        const uint32_t sbase = (uint32_t)(spx * 80 + chalf * 32);
#pragma unroll
        for (int q = 0; q < 4; q++) {
            const uint32_t h0 = cvt_bf16x2(v[4*q+0], v[4*q+1]);
            const uint32_t h1 = cvt_bf16x2(v[4*q+2], v[4*q+3]);
            const float r0 = v[4*q+0] - __uint_as_float(h0 << 16);
            const float r1 = v[4*q+1] - __uint_as_float(h0 & 0xffff0000u);
            const float r2 = v[4*q+2] - __uint_as_float(h1 << 16);
            const float r3 = v[4*q+3] - __uint_as_float(h1 & 0xffff0000u);
            *(uint2*)(buf + OFF_A_HI + sbase + q * 8) = make_uint2(h0, h1);
            *(uint2*)(buf + OFF_A_LO + sbase + q * 8) =
                make_uint2(cvt_bf16x2(r0, r1), cvt_bf16x2(r2, r3));
        }
        // B: cp.async pre-split weights (256 f x 32 k) -- 8 cp16/thread
#pragma unroll
        for (int t2 = 0; t2 < 2; t2++) {
            const int pid = tid + t2 * 256;
            const int row = pid >> 1, bh = pid & 1;
            const size_t src = ((size_t)(i * 256 + row) * 16) + bh * 8;
            const uint32_t dH = sb + bi * BUF_SZ + OFF_B_HI + row * 80 + bh * 32;
            const uint32_t dL = sb + bi * BUF_SZ + OFF_B_LO + row * 80 + bh * 32;
            cp16(dH,      &g_wbh[src]);
            cp16(dH + 16, &g_wbh[src + 4]);
            cp16(dL,      &g_wbl[src]);
            cp16(dL + 16, &g_wbl[src + 4]);
        }
        CP_COMMIT();
    };

    // ---- prologue ----
    if (tid < 128) compute_meta(smem, p0, tid, 0, 0);
    __syncthreads();
    stage(0);

    for (int i = 0; i < 72; i++) {
        CP_WAIT0();
        __syncthreads();
        if (i < 71) stage(i + 1);
        if ((i & 7) == 6 && i < 64) {
            const int ntap = (i >> 3) + 1;
            if (tid < 128) compute_meta(smem, p0, tid, ntap, ntap & 1);
        }
        // ---- MMA burst for chunk i ----
        const uint32_t bufb = sb + (i & 1) * BUF_SZ;
#pragma unroll
        for (int ks = 0; ks < 2; ks++) {
            uint32_t bH[4][4], bL[4][4];
#pragma unroll
            for (int np = 0; np < 4; np++) {
                const uint32_t bo = (b_row + np * 640 + ks * 16) * 2;
                ldsm4(bH[np], bufb + OFF_B_HI + bo);
                ldsm4(bL[np], bufb + OFF_B_LO + bo);
            }
#pragma unroll
            for (int mt = 0; mt < 4; mt++) {
                uint32_t aH[4], aL[4];
                const uint32_t ao = (a_row + mt * 640 + ks * 16) * 2;
                ldsm4(aH, bufb + OFF_A_HI + ao);
                ldsm4(aL, bufb + OFF_A_LO + ao);
#pragma unroll
                for (int nt = 0; nt < 8; nt++) {
                    const int np = nt >> 1, s = (nt & 1) * 2;
                    mma_bf16(acc[mt][nt], aH, bH[np][s], bH[np][s + 1]);
                    mma_bf16(acc[mt][nt], aL, bH[np][s], bH[np][s + 1]);
                    mma_bf16(acc[mt][nt], aH, bL[np][s], bL[np][s + 1]);
                }
            }
        }
    }

    // ---- epilogue: + bias, store ----
    const int gid = lane >> 2, tig = lane & 3;
#pragma unroll
    for (int mt = 0; mt < 4; mt++) {
        const int row0 = p0 + wm * 64 + mt * 16 + gid;
#pragma unroll
        for (int nt = 0; nt < 8; nt++) {
            const int f0 = wn * 64 + nt * 8 + 2 * tig;
            const float2 bcv = *(const float2*)(b_conv + f0);
            float2 o0, o1;
            o0.x = acc[mt][nt][0] + bcv.x;
            o0.y = acc[mt][nt][1] + bcv.y;
            o1.x = acc[mt][nt][2] + bcv.x;
            o1.y = acc[mt][nt][3] + bcv.y;
            *(float2*)(out + (size_t)row0 * Ff + f0) = o0;
            *(float2*)(out + (size_t)(row0 + 8) * Ff + f0) = o1;
        }
    }
}

// ===================== launch ==============================================
extern "C" void kernel_launch(void* const* d_in, const int* in_sizes, int n_in,
                              void* d_out, int out_size)
{
    (void)in_sizes; (void)n_in; (void)out_size;
    const float* x      = (const float*)d_in[0];
    const float* w_off  = (const float*)d_in[1];
    const float* b_off  = (const float*)d_in[2];
    const float* w_conv = (const float*)d_in[3];
    const float* b_conv = (const float*)d_in[4];
    float* out = (float*)d_out;

    cudaFuncSetAttribute(dcn_mma_kernel,
                         cudaFuncAttributeMaxDynamicSharedMemorySize, SMEM_SZ);
    cudaFuncSetAttribute(offset_mma_kernel,
                         cudaFuncAttributeMaxDynamicSharedMemorySize, OB_SMEM);

    prep_w_kernel<<<1152, 256>>>(w_conv);
    prep_woff_kernel<<<144, 256>>>(w_off);
    prep_x_kernel<<<XWORDS / 256, 256>>>(x);
    offset_mma_kernel<<<288, 256, OB_SMEM>>>(b_off);
    dcn_mma_kernel<<<288, 256, SMEM_SZ>>>(x, b_conv, out);
}

// round 8
// speedup vs baseline: 3.3011x; 1.2698x over previous
#include <cuda_runtime.h>
#include <cuda_fp16.h>
#include <math.h>
#include <stdint.h>

#define Bb 4
#define Hh 96
#define Ww 96
#define Cc 256
#define Ff 256

// ===================== mma.sync helpers =====================================
__device__ __forceinline__ uint32_t smem_u32(const void* p) {
    uint32_t a;
    asm("{ .reg .u64 t; cvta.to.shared.u64 t, %1; cvt.u32.u64 %0, t; }"
        : "=r"(a) : "l"(p));
    return a;
}
__device__ __forceinline__ void ldsm4(uint32_t* r, uint32_t addr) {
    asm volatile("ldmatrix.sync.aligned.m8n8.x4.shared.b16 {%0,%1,%2,%3}, [%4];"
        : "=r"(r[0]), "=r"(r[1]), "=r"(r[2]), "=r"(r[3]) : "r"(addr));
}
__device__ __forceinline__ void mma_f16(float* d, const uint32_t* a,
                                        uint32_t b0, uint32_t b1) {
    asm volatile(
        "mma.sync.aligned.m16n8k16.row.col.f32.f16.f16.f32 "
        "{%0,%1,%2,%3}, {%4,%5,%6,%7}, {%8,%9}, {%0,%1,%2,%3};"
        : "+f"(d[0]), "+f"(d[1]), "+f"(d[2]), "+f"(d[3])
        : "r"(a[0]), "r"(a[1]), "r"(a[2]), "r"(a[3]), "r"(b0), "r"(b1));
}
// pack two floats to f16x2 (lo half = v0)
__device__ __forceinline__ uint32_t f16x2_of(float v0, float v1) {
    __half2 h = __floats2half2_rn(v0, v1);
    return *(uint32_t*)&h;
}
__device__ __forceinline__ float2 f16x2_tof(uint32_t w) {
    __half2 h = *(__half2*)&w;
    return __half22float2(h);
}
__device__ __forceinline__ void cp16(uint32_t dst, const void* src) {
    asm volatile("cp.async.cg.shared.global [%0], [%1], 16;"
                 :: "r"(dst), "l"(src));
}
__device__ __forceinline__ void cp16z(uint32_t dst, const void* src, int sz) {
    asm volatile("cp.async.cg.shared.global [%0], [%1], 16, %2;"
                 :: "r"(dst), "l"(src), "r"(sz));
}
#define CP_COMMIT() asm volatile("cp.async.commit_group;" ::: "memory")
#define CP_WAIT0()  asm volatile("cp.async.wait_group 0;" ::: "memory")

// ===================== device scratch =======================================
__device__ float g_om[Bb * Hh * Ww * 27];          // dy[9], dx[9], sig(mask)[9]
// w_conv fp16 (hi only), layout [chunk=72][f=256][16 x f16x2 along k]
__device__ uint32_t g_wbh[72 * 256 * 16];
// w_off fp16 (hi only), layout [chunk=72][f=32 (27 used)][16 x f16x2]
__device__ uint32_t g_wobh[72 * 32 * 16];
// x fp16 split, f16x2 words over channel pairs
#define XWORDS (Bb * Hh * Ww * Cc / 2)
__device__ uint32_t g_xh[XWORDS];
__device__ uint32_t g_xl[XWORDS];

// ===================== prep kernels =========================================
__global__ __launch_bounds__(256) void prep_w_kernel(const float* __restrict__ w_conv)
{
    const int g = blockIdx.x * 256 + threadIdx.x;    // 0 .. 294911
    const int kp = g & 15;
    const int f  = (g >> 4) & 255;
    const int chunk = g >> 12;       // 0..71
    const int tap = chunk >> 3, cc = chunk & 7;
    const int c = cc * 32 + 2 * kp;
    const float v0 = w_conv[((size_t)(tap * Cc + c)     * Ff) + f];
    const float v1 = w_conv[((size_t)(tap * Cc + c + 1) * Ff) + f];
    g_wbh[(chunk * 256 + f) * 16 + kp] = f16x2_of(v0, v1);
}

__global__ __launch_bounds__(256) void prep_woff_kernel(const float* __restrict__ w_off)
{
    const int g = blockIdx.x * 256 + threadIdx.x;    // 0 .. 36863
    const int kp = g & 15;
    const int f  = (g >> 4) & 31;
    const int chunk = g >> 9;        // 0..71
    const int tap = chunk >> 3, cc = chunk & 7;
    const int c = cc * 32 + 2 * kp;
    float v0 = 0.f, v1 = 0.f;
    if (f < 27) {
        v0 = w_off[((size_t)(tap * Cc + c)     * 27) + f];
        v1 = w_off[((size_t)(tap * Cc + c + 1) * 27) + f];
    }
    g_wobh[(chunk * 32 + f) * 16 + kp] = f16x2_of(v0, v1);
}

__global__ __launch_bounds__(256) void prep_x_kernel(const float* __restrict__ x)
{
    const int i = blockIdx.x * 256 + threadIdx.x;    // 0 .. XWORDS-1
    const float2 v = ((const float2*)x)[i];
    const uint32_t hw = f16x2_of(v.x, v.y);
    const float2 hf = f16x2_tof(hw);
    g_xh[i] = hw;
    g_xl[i] = f16x2_of(v.x - hf.x, v.y - hf.y);
}

// ===================== Kernel A: offset conv via mma.sync ===================
// CTA: 128 px x 32 f (27 used); 8 warps, each 16 px x 32 f. Double-buffered.
#define OB_A_HI 0
#define OB_A_LO 10240
#define OB_B_HI 20480
#define OB_BUF  23040
#define OB_SMEM (2 * OB_BUF)     // 46080

__global__ __launch_bounds__(256) void offset_mma_kernel(
    const float* __restrict__ b_off)
{
    extern __shared__ __align__(16) char smem[];
    const uint32_t sb = smem_u32(smem);
    const int tid  = threadIdx.x;
    const int warp = tid >> 5;
    const int lane = tid & 31;
    const int p0 = blockIdx.x * 128;

    float acc[4][4];
#pragma unroll
    for (int nt = 0; nt < 4; nt++)
#pragma unroll
        for (int q = 0; q < 4; q++) acc[nt][q] = 0.f;

    const int spx = tid >> 1;
    const int h16 = tid & 1;
    const int p = p0 + spx;
    const int wpix = p % Ww;
    const int hw_  = p / Ww;
    const int hh = hw_ % Hh;
    const int bimg = hw_ / Hh;

    const uint32_t a_row = (uint32_t)((warp * 16 + (lane & 15)) * 40 + (lane >> 4) * 8);
    const uint32_t b_row = (uint32_t)(((lane & 7) + ((lane >> 4) << 3)) * 40
                                      + ((lane >> 3) & 1) * 8);

    auto stage = [&](int i) {
        const int tap = i >> 3, cc = i & 7;
        const uint32_t bufb = sb + (i & 1) * OB_BUF;
        const int ky = tap / 3, kx = tap % 3;
        const int y  = hh + ky - 1;
        const int xw = wpix + kx - 1;
        const bool valid = (y >= 0) && (y < Hh) && (xw >= 0) && (xw < Ww);
        const int yc = valid ? y : 0, xc = valid ? xw : 0;
        const size_t srcw = ((((size_t)(bimg * Hh + yc) * Ww + xc) * Cc)
                             + cc * 32 + h16 * 16) >> 1;
        const int sz = valid ? 16 : 0;
        const uint32_t dA = bufb + OB_A_HI + spx * 80 + h16 * 32;
        const uint32_t dL = bufb + OB_A_LO + spx * 80 + h16 * 32;
        cp16z(dA,      &g_xh[srcw],     sz);
        cp16z(dA + 16, &g_xh[srcw + 4], sz);
        cp16z(dL,      &g_xl[srcw],     sz);
        cp16z(dL + 16, &g_xl[srcw + 4], sz);
        if (tid < 64) {
            const int row = tid >> 1, bh = tid & 1;
            const size_t s2 = ((size_t)(i * 32 + row) * 16) + bh * 8;
            const uint32_t dbh = bufb + OB_B_HI + row * 80 + bh * 32;
            cp16(dbh,      &g_wobh[s2]);
            cp16(dbh + 16, &g_wobh[s2 + 4]);
        }
        CP_COMMIT();
    };

    stage(0);
    for (int i = 0; i < 72; i++) {
        CP_WAIT0();
        __syncthreads();
        if (i < 71) stage(i + 1);
        const uint32_t bufb = sb + (i & 1) * OB_BUF;
#pragma unroll
        for (int ks = 0; ks < 2; ks++) {
            uint32_t aH[4], aL[4], bH[2][4];
            ldsm4(aH, bufb + OB_A_HI + (a_row + ks * 16) * 2);
            ldsm4(aL, bufb + OB_A_LO + (a_row + ks * 16) * 2);
#pragma unroll
            for (int np = 0; np < 2; np++)
                ldsm4(bH[np], bufb + OB_B_HI + (b_row + np * 640 + ks * 16) * 2);
#pragma unroll
            for (int nt = 0; nt < 4; nt++) {
                const int np = nt >> 1, s = (nt & 1) * 2;
                mma_f16(acc[nt], aH, bH[np][s], bH[np][s + 1]);
                mma_f16(acc[nt], aL, bH[np][s], bH[np][s + 1]);
            }
        }
    }

    // epilogue: bias + sigmoid(mask) -> g_om
    const int gid = lane >> 2, tig = lane & 3;
    const int row0 = p0 + warp * 16 + gid;
#pragma unroll
    for (int nt = 0; nt < 4; nt++) {
        const int col = nt * 8 + 2 * tig;
#pragma unroll
        for (int e = 0; e < 2; e++) {
            const int c = col + e;
            if (c < 27) {
                const float bo = b_off[c];
                float v0 = acc[nt][e] + bo;
                float v1 = acc[nt][2 + e] + bo;
                if (c >= 18) {
                    v0 = 1.f / (1.f + expf(-v0));
                    v1 = 1.f / (1.f + expf(-v1));
                }
                g_om[(size_t)row0 * 27 + c] = v0;
                g_om[(size_t)(row0 + 8) * 27 + c] = v1;
            }
        }
    }
}

// ===================== Kernel B: pipelined mma.sync deformable GEMM =========
// CTA: 128 px x 256 f; double-buffered; fp16 2-term split (A only).
#define BUF_SZ   40960        // A_HI|A_LO (10240 each) | B_HI (20480)
#define OFF_A_HI 0
#define OFF_A_LO 10240
#define OFF_B_HI 20480
#define OFF_META 81920        // 2 x (MW 2048 | MI 2048)
#define SMEM_SZ  90112

__device__ __forceinline__ void compute_meta(char* smem, int p0, int px,
                                             int tap, int mbuf) {
    const int p = p0 + px;
    const int wpix = p % Ww;
    const int hw_  = p / Ww;
    const int h = hw_ % Hh;
    const int b = hw_ / Hh;
    const float* om = g_om + (size_t)p * 27;
    const float dy = om[tap], dx = om[9 + tap], mask = om[18 + tap];
    const int ky = tap / 3, kx = tap % 3;
    const float ys = (float)(h + ky - 1) + dy;
    const float xs = (float)(wpix + kx - 1) + dx;
    const float y0f = floorf(ys), x0f = floorf(xs);
    const float wy1 = ys - y0f, wx1 = xs - x0f;
    const float wy0 = 1.f - wy1, wx0 = 1.f - wx1;
    const int y0 = (int)y0f, x0i = (int)x0f;
    const int y1 = y0 + 1,   x1i = x0i + 1;
    const bool vy0 = (y0  >= 0) && (y0  < Hh);
    const bool vy1 = (y1  >= 0) && (y1  < Hh);
    const bool vx0 = (x0i >= 0) && (x0i < Ww);
    const bool vx1 = (x1i >= 0) && (x1i < Ww);
    const float c00 = (vy0 && vx0) ? wy0 * wx0 * mask : 0.f;
    const float c01 = (vy0 && vx1) ? wy0 * wx1 * mask : 0.f;
    const float c10 = (vy1 && vx0) ? wy1 * wx0 * mask : 0.f;
    const float c11 = (vy1 && vx1) ? wy1 * wx1 * mask : 0.f;
    const int y0c = min(max(y0, 0), Hh - 1), y1c = min(max(y1, 0), Hh - 1);
    const int x0c = min(max(x0i, 0), Ww - 1), x1c = min(max(x1i, 0), Ww - 1);
    const int r0 = (b * Hh + y0c) * Ww, r1 = (b * Hh + y1c) * Ww;
    char* mb = smem + OFF_META + mbuf * 4096;
    *(float4*)(mb + px * 16) = make_float4(c00, c01, c10, c11);
    *(int4*)(mb + 2048 + px * 16) =
        make_int4((r0 + x0c) * Cc, (r0 + x1c) * Cc,
                  (r1 + x0c) * Cc, (r1 + x1c) * Cc);
}

__global__ __launch_bounds__(256, 1) void dcn_mma_kernel(
    const float* __restrict__ x, const float* __restrict__ b_conv,
    float* __restrict__ out)
{
    extern __shared__ __align__(16) char smem[];
    const uint32_t sb = smem_u32(smem);

    const int tid  = threadIdx.x;
    const int warp = tid >> 5;
    const int lane = tid & 31;
    const int wm = warp >> 2;        // 0..1 (M 64)
    const int wn = warp & 3;         // 0..3 (N 64)
    const int p0 = blockIdx.x * 128;

    float acc[4][8][4];
#pragma unroll
    for (int mt = 0; mt < 4; mt++)
#pragma unroll
        for (int nt = 0; nt < 8; nt++)
#pragma unroll
            for (int q = 0; q < 4; q++) acc[mt][nt][q] = 0.f;

    const uint32_t a_row = (uint32_t)((wm * 64 + (lane & 15)) * 40 + (lane >> 4) * 8);
    const uint32_t b_row = (uint32_t)((wn * 64 + (lane & 7) + ((lane >> 4) << 3)) * 40
                                      + ((lane >> 3) & 1) * 8);

    const int spx   = tid >> 1;      // staging pixel
    const int chalf = tid & 1;       // staging channel half (16 c)

    auto stage = [&](int i) {
        const int tap = i >> 3, cc = i & 7;
        const int bi = i & 1;
        char* buf = smem + bi * BUF_SZ;
        const char* mb = smem + OFF_META + (tap & 1) * 4096;
        const float4 cw = *(const float4*)(mb + spx * 16);
        const int4   ai = *(const int4*)(mb + 2048 + spx * 16);
        // A: gather + bilinear + fp16 split
        const int cg = cc * 32 + chalf * 16;
        float v[16];
#pragma unroll
        for (int q = 0; q < 4; q++) {
            const float4 p00 = *(const float4*)(x + ai.x + cg + 4 * q);
            const float4 p01 = *(const float4*)(x + ai.y + cg + 4 * q);
            const float4 p10 = *(const float4*)(x + ai.z + cg + 4 * q);
            const float4 p11 = *(const float4*)(x + ai.w + cg + 4 * q);
            v[4*q+0] = cw.x*p00.x + cw.y*p01.x + cw.z*p10.x + cw.w*p11.x;
            v[4*q+1] = cw.x*p00.y + cw.y*p01.y + cw.z*p10.y + cw.w*p11.y;
            v[4*q+2] = cw.x*p00.z + cw.y*p01.z + cw.z*p10.z + cw.w*p11.z;
            v[4*q+3] = cw.x*p00.w + cw.y*p01.w + cw.z*p10.w + cw.w*p11.w;
        }
        const uint32_t sbase = (uint32_t)(spx * 80 + chalf * 32);
#pragma unroll
        for (int q = 0; q < 4; q++) {
            const uint32_t h0 = f16x2_of(v[4*q+0], v[4*q+1]);
            const uint32_t h1 = f16x2_of(v[4*q+2], v[4*q+3]);
            const float2 f0 = f16x2_tof(h0);
            const float2 f1 = f16x2_tof(h1);
            *(uint2*)(buf + OFF_A_HI + sbase + q * 8) = make_uint2(h0, h1);
            *(uint2*)(buf + OFF_A_LO + sbase + q * 8) =
                make_uint2(f16x2_of(v[4*q+0] - f0.x, v[4*q+1] - f0.y),
                           f16x2_of(v[4*q+2] - f1.x, v[4*q+3] - f1.y));
        }
        // B: cp.async fp16 weights (256 f x 32 k) -- 4 cp16/thread
#pragma unroll
        for (int t2 = 0; t2 < 2; t2++) {
            const int pid = tid + t2 * 256;
            const int row = pid >> 1, bh = pid & 1;
            const size_t src = ((size_t)(i * 256 + row) * 16) + bh * 8;
            const uint32_t dH = sb + bi * BUF_SZ + OFF_B_HI + row * 80 + bh * 32;
            cp16(dH,      &g_wbh[src]);
            cp16(dH + 16, &g_wbh[src + 4]);
        }
        CP_COMMIT();
    };

    // ---- prologue ----
    if (tid < 128) compute_meta(smem, p0, tid, 0, 0);
    __syncthreads();
    stage(0);

    for (int i = 0; i < 72; i++) {
        CP_WAIT0();
        __syncthreads();
        if (i < 71) stage(i + 1);
        if ((i & 7) == 6 && i < 64) {
            const int ntap = (i >> 3) + 1;
            if (tid < 128) compute_meta(smem, p0, tid, ntap, ntap & 1);
        }
        // ---- MMA burst for chunk i ----
        const uint32_t bufb = sb + (i & 1) * BUF_SZ;
#pragma unroll
        for (int ks = 0; ks < 2; ks++) {
            uint32_t bH[4][4];
#pragma unroll
            for (int np = 0; np < 4; np++)
                ldsm4(bH[np], bufb + OFF_B_HI + (b_row + np * 640 + ks * 16) * 2);
#pragma unroll
            for (int mt = 0; mt < 4; mt++) {
                uint32_t aH[4], aL[4];
                const uint32_t ao = (a_row + mt * 640 + ks * 16) * 2;
                ldsm4(aH, bufb + OFF_A_HI + ao);
                ldsm4(aL, bufb + OFF_A_LO + ao);
#pragma unroll
                for (int nt = 0; nt < 8; nt++) {
                    const int np = nt >> 1, s = (nt & 1) * 2;
                    mma_f16(acc[mt][nt], aH, bH[np][s], bH[np][s + 1]);
                    mma_f16(acc[mt][nt], aL, bH[np][s], bH[np][s + 1]);
                }
            }
        }
    }

    // ---- epilogue: + bias, store ----
    const int gid = lane >> 2, tig = lane & 3;
#pragma unroll
    for (int mt = 0; mt < 4; mt++) {
        const int row0 = p0 + wm * 64 + mt * 16 + gid;
#pragma unroll
        for (int nt = 0; nt < 8; nt++) {
            const int f0 = wn * 64 + nt * 8 + 2 * tig;
            const float2 bcv = *(const float2*)(b_conv + f0);
            float2 o0, o1;
            o0.x = acc[mt][nt][0] + bcv.x;
            o0.y = acc[mt][nt][1] + bcv.y;
            o1.x = acc[mt][nt][2] + bcv.x;
            o1.y = acc[mt][nt][3] + bcv.y;
            *(float2*)(out + (size_t)row0 * Ff + f0) = o0;
            *(float2*)(out + (size_t)(row0 + 8) * Ff + f0) = o1;
        }
    }
}

// ===================== launch ==============================================
extern "C" void kernel_launch(void* const* d_in, const int* in_sizes, int n_in,
                              void* d_out, int out_size)
{
    (void)in_sizes; (void)n_in; (void)out_size;
    const float* x      = (const float*)d_in[0];
    const float* w_off  = (const float*)d_in[1];
    const float* b_off  = (const float*)d_in[2];
    const float* w_conv = (const float*)d_in[3];
    const float* b_conv = (const float*)d_in[4];
    float* out = (float*)d_out;

    cudaFuncSetAttribute(dcn_mma_kernel,
                         cudaFuncAttributeMaxDynamicSharedMemorySize, SMEM_SZ);
    cudaFuncSetAttribute(offset_mma_kernel,
                         cudaFuncAttributeMaxDynamicSharedMemorySize, OB_SMEM);

    prep_w_kernel<<<1152, 256>>>(w_conv);
    prep_woff_kernel<<<144, 256>>>(w_off);
    prep_x_kernel<<<XWORDS / 256, 256>>>(x);
    offset_mma_kernel<<<288, 256, OB_SMEM>>>(b_off);
    dcn_mma_kernel<<<288, 256, SMEM_SZ>>>(x, b_conv, out);
}

// round 9
// speedup vs baseline: 3.4573x; 1.0473x over previous
#include <cuda_runtime.h>
#include <cuda_fp16.h>
#include <math.h>
#include <stdint.h>

#define Bb 4
#define Hh 96
#define Ww 96
#define Cc 256
#define Ff 256

// ===================== mma.sync helpers =====================================
__device__ __forceinline__ uint32_t smem_u32(const void* p) {
    uint32_t a;
    asm("{ .reg .u64 t; cvta.to.shared.u64 t, %1; cvt.u32.u64 %0, t; }"
        : "=r"(a) : "l"(p));
    return a;
}
__device__ __forceinline__ void ldsm4(uint32_t* r, uint32_t addr) {
    asm volatile("ldmatrix.sync.aligned.m8n8.x4.shared.b16 {%0,%1,%2,%3}, [%4];"
        : "=r"(r[0]), "=r"(r[1]), "=r"(r[2]), "=r"(r[3]) : "r"(addr));
}
__device__ __forceinline__ void mma_f16(float* d, const uint32_t* a,
                                        uint32_t b0, uint32_t b1) {
    asm volatile(
        "mma.sync.aligned.m16n8k16.row.col.f32.f16.f16.f32 "
        "{%0,%1,%2,%3}, {%4,%5,%6,%7}, {%8,%9}, {%0,%1,%2,%3};"
        : "+f"(d[0]), "+f"(d[1]), "+f"(d[2]), "+f"(d[3])
        : "r"(a[0]), "r"(a[1]), "r"(a[2]), "r"(a[3]), "r"(b0), "r"(b1));
}
__device__ __forceinline__ uint32_t f16x2_of(float v0, float v1) {
    __half2 h = __floats2half2_rn(v0, v1);
    return *(uint32_t*)&h;
}
__device__ __forceinline__ float2 f16x2_tof(uint32_t w) {
    __half2 h = *(__half2*)&w;
    return __half22float2(h);
}
__device__ __forceinline__ void cp16(uint32_t dst, const void* src) {
    asm volatile("cp.async.cg.shared.global [%0], [%1], 16;"
                 :: "r"(dst), "l"(src));
}
__device__ __forceinline__ void cp16z(uint32_t dst, const void* src, int sz) {
    asm volatile("cp.async.cg.shared.global [%0], [%1], 16, %2;"
                 :: "r"(dst), "l"(src), "r"(sz));
}
#define CP_COMMIT() asm volatile("cp.async.commit_group;" ::: "memory")
#define CP_WAIT0()  asm volatile("cp.async.wait_group 0;" ::: "memory")
#define CP_WAIT2()  asm volatile("cp.async.wait_group 2;" ::: "memory")

// ===================== device scratch =======================================
__device__ float g_om[Bb * Hh * Ww * 27];          // dy[9], dx[9], sig(mask)[9]
__device__ uint32_t g_wbh[72 * 256 * 16];          // w_conv fp16 [chunk][f][k/2]
__device__ uint32_t g_wobh[72 * 32 * 16];          // w_off  fp16 [chunk][f][k/2]
#define XWORDS (Bb * Hh * Ww * Cc / 2)
__device__ uint32_t g_xh[XWORDS];                  // x fp16 hi
__device__ uint32_t g_xl[XWORDS];                  // x fp16 lo (residual)

// ===================== prep kernels =========================================
__global__ __launch_bounds__(256) void prep_w_kernel(const float* __restrict__ w_conv)
{
    const int g = blockIdx.x * 256 + threadIdx.x;
    const int kp = g & 15;
    const int f  = (g >> 4) & 255;
    const int chunk = g >> 12;
    const int tap = chunk >> 3, cc = chunk & 7;
    const int c = cc * 32 + 2 * kp;
    const float v0 = w_conv[((size_t)(tap * Cc + c)     * Ff) + f];
    const float v1 = w_conv[((size_t)(tap * Cc + c + 1) * Ff) + f];
    g_wbh[(chunk * 256 + f) * 16 + kp] = f16x2_of(v0, v1);
}

__global__ __launch_bounds__(256) void prep_woff_kernel(const float* __restrict__ w_off)
{
    const int g = blockIdx.x * 256 + threadIdx.x;
    const int kp = g & 15;
    const int f  = (g >> 4) & 31;
    const int chunk = g >> 9;
    const int tap = chunk >> 3, cc = chunk & 7;
    const int c = cc * 32 + 2 * kp;
    float v0 = 0.f, v1 = 0.f;
    if (f < 27) {
        v0 = w_off[((size_t)(tap * Cc + c)     * 27) + f];
        v1 = w_off[((size_t)(tap * Cc + c + 1) * 27) + f];
    }
    g_wobh[(chunk * 32 + f) * 16 + kp] = f16x2_of(v0, v1);
}

__global__ __launch_bounds__(256) void prep_x_kernel(const float* __restrict__ x)
{
    const int i = blockIdx.x * 256 + threadIdx.x;
    const float2 v = ((const float2*)x)[i];
    const uint32_t hw = f16x2_of(v.x, v.y);
    const float2 hf = f16x2_tof(hw);
    g_xh[i] = hw;
    g_xl[i] = f16x2_of(v.x - hf.x, v.y - hf.y);
}

// ===================== Kernel A: offset conv, 4-stage cp.async ring =========
#define OB_A_HI 0
#define OB_A_LO 10240
#define OB_B_HI 20480
#define OB_BUF  23040
#define OB_SMEM (4 * OB_BUF)     // 92160

__global__ __launch_bounds__(256) void offset_mma_kernel(
    const float* __restrict__ b_off)
{
    extern __shared__ __align__(16) char smem[];
    const uint32_t sb = smem_u32(smem);
    const int tid  = threadIdx.x;
    const int warp = tid >> 5;
    const int lane = tid & 31;
    const int p0 = blockIdx.x * 128;

    float acc[4][4];
#pragma unroll
    for (int nt = 0; nt < 4; nt++)
#pragma unroll
        for (int q = 0; q < 4; q++) acc[nt][q] = 0.f;

    const int spx = tid >> 1;
    const int h16 = tid & 1;
    const int p = p0 + spx;
    const int wpix = p % Ww;
    const int hw_  = p / Ww;
    const int hh = hw_ % Hh;
    const int bimg = hw_ / Hh;

    const uint32_t a_row = (uint32_t)((warp * 16 + (lane & 15)) * 40 + (lane >> 4) * 8);
    const uint32_t b_row = (uint32_t)(((lane & 7) + ((lane >> 4) << 3)) * 40
                                      + ((lane >> 3) & 1) * 8);

    auto stage = [&](int i) {
        const int tap = i >> 3, cc = i & 7;
        const uint32_t bufb = sb + (i & 3) * OB_BUF;
        const int ky = tap / 3, kx = tap % 3;
        const int y  = hh + ky - 1;
        const int xw = wpix + kx - 1;
        const bool valid = (y >= 0) && (y < Hh) && (xw >= 0) && (xw < Ww);
        const int yc = valid ? y : 0, xc = valid ? xw : 0;
        const size_t srcw = ((((size_t)(bimg * Hh + yc) * Ww + xc) * Cc)
                             + cc * 32 + h16 * 16) >> 1;
        const int sz = valid ? 16 : 0;
        const uint32_t dA = bufb + OB_A_HI + spx * 80 + h16 * 32;
        const uint32_t dL = bufb + OB_A_LO + spx * 80 + h16 * 32;
        cp16z(dA,      &g_xh[srcw],     sz);
        cp16z(dA + 16, &g_xh[srcw + 4], sz);
        cp16z(dL,      &g_xl[srcw],     sz);
        cp16z(dL + 16, &g_xl[srcw + 4], sz);
        if (tid < 64) {
            const int row = tid >> 1, bh = tid & 1;
            const size_t s2 = ((size_t)(i * 32 + row) * 16) + bh * 8;
            const uint32_t dbh = bufb + OB_B_HI + row * 80 + bh * 32;
            cp16(dbh,      &g_wobh[s2]);
            cp16(dbh + 16, &g_wobh[s2 + 4]);
        }
        CP_COMMIT();
    };

    stage(0); stage(1); stage(2);
    for (int i = 0; i < 72; i++) {
        CP_WAIT2();               // group i done; i+1, i+2 may remain in flight
        __syncthreads();          // all warps done MMA(i-1), buffers coherent
        if (i < 69) stage(i + 3); // overwrites buffer (i-1)&3 — safe after sync
        const uint32_t bufb = sb + (i & 3) * OB_BUF;
#pragma unroll
        for (int ks = 0; ks < 2; ks++) {
            uint32_t aH[4], aL[4], bH[2][4];
            ldsm4(aH, bufb + OB_A_HI + (a_row + ks * 16) * 2);
            ldsm4(aL, bufb + OB_A_LO + (a_row + ks * 16) * 2);
#pragma unroll
            for (int np = 0; np < 2; np++)
                ldsm4(bH[np], bufb + OB_B_HI + (b_row + np * 640 + ks * 16) * 2);
#pragma unroll
            for (int nt = 0; nt < 4; nt++) {
                const int np = nt >> 1, s = (nt & 1) * 2;
                mma_f16(acc[nt], aH, bH[np][s], bH[np][s + 1]);
                mma_f16(acc[nt], aL, bH[np][s], bH[np][s + 1]);
            }
        }
    }

    // epilogue: bias + sigmoid(mask) -> g_om
    const int gid = lane >> 2, tig = lane & 3;
    const int row0 = p0 + warp * 16 + gid;
#pragma unroll
    for (int nt = 0; nt < 4; nt++) {
        const int col = nt * 8 + 2 * tig;
#pragma unroll
        for (int e = 0; e < 2; e++) {
            const int c = col + e;
            if (c < 27) {
                const float bo = b_off[c];
                float v0 = acc[nt][e] + bo;
                float v1 = acc[nt][2 + e] + bo;
                if (c >= 18) {
                    v0 = 1.f / (1.f + expf(-v0));
                    v1 = 1.f / (1.f + expf(-v1));
                }
                g_om[(size_t)row0 * 27 + c] = v0;
                g_om[(size_t)(row0 + 8) * 27 + c] = v1;
            }
        }
    }
}

// ===================== Kernel B: deformable GEMM, reg-prefetched gather =====
#define BUF_SZ   40960        // A_HI|A_LO (10240 each) | B_HI (20480)
#define OFF_A_HI 0
#define OFF_A_LO 10240
#define OFF_B_HI 20480
#define OFF_META 81920        // 2 x (MW 2048 | MI 2048)
#define SMEM_SZ  90112

__device__ __forceinline__ void compute_meta(char* smem, int p0, int px,
                                             int tap, int mbuf) {
    const int p = p0 + px;
    const int wpix = p % Ww;
    const int hw_  = p / Ww;
    const int h = hw_ % Hh;
    const int b = hw_ / Hh;
    const float* om = g_om + (size_t)p * 27;
    const float dy = om[tap], dx = om[9 + tap], mask = om[18 + tap];
    const int ky = tap / 3, kx = tap % 3;
    const float ys = (float)(h + ky - 1) + dy;
    const float xs = (float)(wpix + kx - 1) + dx;
    const float y0f = floorf(ys), x0f = floorf(xs);
    const float wy1 = ys - y0f, wx1 = xs - x0f;
    const float wy0 = 1.f - wy1, wx0 = 1.f - wx1;
    const int y0 = (int)y0f, x0i = (int)x0f;
    const int y1 = y0 + 1,   x1i = x0i + 1;
    const bool vy0 = (y0  >= 0) && (y0  < Hh);
    const bool vy1 = (y1  >= 0) && (y1  < Hh);
    const bool vx0 = (x0i >= 0) && (x0i < Ww);
    const bool vx1 = (x1i >= 0) && (x1i < Ww);
    const float c00 = (vy0 && vx0) ? wy0 * wx0 * mask : 0.f;
    const float c01 = (vy0 && vx1) ? wy0 * wx1 * mask : 0.f;
    const float c10 = (vy1 && vx0) ? wy1 * wx0 * mask : 0.f;
    const float c11 = (vy1 && vx1) ? wy1 * wx1 * mask : 0.f;
    const int y0c = min(max(y0, 0), Hh - 1), y1c = min(max(y1, 0), Hh - 1);
    const int x0c = min(max(x0i, 0), Ww - 1), x1c = min(max(x1i, 0), Ww - 1);
    const int r0 = (b * Hh + y0c) * Ww, r1 = (b * Hh + y1c) * Ww;
    char* mb = smem + OFF_META + mbuf * 4096;
    *(float4*)(mb + px * 16) = make_float4(c00, c01, c10, c11);
    *(int4*)(mb + 2048 + px * 16) =
        make_int4((r0 + x0c) * Cc, (r0 + x1c) * Cc,
                  (r1 + x0c) * Cc, (r1 + x1c) * Cc);
}

__global__ __launch_bounds__(256, 1) void dcn_mma_kernel(
    const float* __restrict__ x, const float* __restrict__ b_conv,
    float* __restrict__ out)
{
    extern __shared__ __align__(16) char smem[];
    const uint32_t sb = smem_u32(smem);

    const int tid  = threadIdx.x;
    const int warp = tid >> 5;
    const int lane = tid & 31;
    const int wm = warp >> 2;
    const int wn = warp & 3;
    const int p0 = blockIdx.x * 128;

    float acc[4][8][4];
#pragma unroll
    for (int mt = 0; mt < 4; mt++)
#pragma unroll
        for (int nt = 0; nt < 8; nt++)
#pragma unroll
            for (int q = 0; q < 4; q++) acc[mt][nt][q] = 0.f;

    const uint32_t a_row = (uint32_t)((wm * 64 + (lane & 15)) * 40 + (lane >> 4) * 8);
    const uint32_t b_row = (uint32_t)((wn * 64 + (lane & 7) + ((lane >> 4) << 3)) * 40
                                      + ((lane >> 3) & 1) * 8);

    const int spx   = tid >> 1;      // staging pixel
    const int chalf = tid & 1;       // staging channel half (16 c)

    // B copy for chunk i into buffer (i&1)
    auto stage_b = [&](int i) {
#pragma unroll
        for (int t2 = 0; t2 < 2; t2++) {
            const int pid = tid + t2 * 256;
            const int row = pid >> 1, bh = pid & 1;
            const size_t src = ((size_t)(i * 256 + row) * 16) + bh * 8;
            const uint32_t dH = sb + (i & 1) * BUF_SZ + OFF_B_HI + row * 80 + bh * 32;
            cp16(dH,      &g_wbh[src]);
            cp16(dH + 16, &g_wbh[src + 4]);
        }
        CP_COMMIT();
    };
    // convert + STS of prefetched gather for chunk i
    auto stage_sts = [&](int i, const float4 cw,
                         const float4* g00, const float4* g01,
                         const float4* g10, const float4* g11) {
        char* buf = smem + (i & 1) * BUF_SZ;
        const uint32_t sbase = (uint32_t)(spx * 80 + chalf * 32);
#pragma unroll
        for (int q = 0; q < 4; q++) {
            const float v0 = cw.x*g00[q].x + cw.y*g01[q].x + cw.z*g10[q].x + cw.w*g11[q].x;
            const float v1 = cw.x*g00[q].y + cw.y*g01[q].y + cw.z*g10[q].y + cw.w*g11[q].y;
            const float v2 = cw.x*g00[q].z + cw.y*g01[q].z + cw.z*g10[q].z + cw.w*g11[q].z;
            const float v3 = cw.x*g00[q].w + cw.y*g01[q].w + cw.z*g10[q].w + cw.w*g11[q].w;
            const uint32_t h0 = f16x2_of(v0, v1);
            const uint32_t h1 = f16x2_of(v2, v3);
            const float2 f0 = f16x2_tof(h0);
            const float2 f1 = f16x2_tof(h1);
            *(uint2*)(buf + OFF_A_HI + sbase + q * 8) = make_uint2(h0, h1);
            *(uint2*)(buf + OFF_A_LO + sbase + q * 8) =
                make_uint2(f16x2_of(v0 - f0.x, v1 - f0.y),
                           f16x2_of(v2 - f1.x, v3 - f1.y));
        }
    };

    // ---- prologue: meta(0), full stage of chunk 0 ----
    if (tid < 128) compute_meta(smem, p0, tid, 0, 0);
    __syncthreads();
    {
        const char* mb = smem + OFF_META;
        const float4 cw = *(const float4*)(mb + spx * 16);
        const int4   ai = *(const int4*)(mb + 2048 + spx * 16);
        const int cg = chalf * 16;   // chunk 0: cc=0
        float4 g00[4], g01[4], g10[4], g11[4];
#pragma unroll
        for (int q = 0; q < 4; q++) {
            g00[q] = *(const float4*)(x + ai.x + cg + 4 * q);
            g01[q] = *(const float4*)(x + ai.y + cg + 4 * q);
            g10[q] = *(const float4*)(x + ai.z + cg + 4 * q);
            g11[q] = *(const float4*)(x + ai.w + cg + 4 * q);
        }
        stage_sts(0, cw, g00, g01, g10, g11);
        stage_b(0);
    }

    for (int i = 0; i < 72; i++) {
        CP_WAIT0();
        __syncthreads();

        // prefetch gather for i+1 into registers; launch B copy for i+1
        float4 g00[4], g01[4], g10[4], g11[4];
        float4 cwn;
        const int inext = i + 1;
        if (inext < 72) {
            const int tapn = inext >> 3, ccn = inext & 7;
            const char* mb = smem + OFF_META + (tapn & 1) * 4096;
            cwn = *(const float4*)(mb + spx * 16);
            const int4 ain = *(const int4*)(mb + 2048 + spx * 16);
            const int cg = ccn * 32 + chalf * 16;
#pragma unroll
            for (int q = 0; q < 4; q++) {
                g00[q] = *(const float4*)(x + ain.x + cg + 4 * q);
                g01[q] = *(const float4*)(x + ain.y + cg + 4 * q);
                g10[q] = *(const float4*)(x + ain.z + cg + 4 * q);
                g11[q] = *(const float4*)(x + ain.w + cg + 4 * q);
            }
            stage_b(inext);
        }

        // ---- MMA burst for chunk i (hides prefetch LDG latency) ----
        const uint32_t bufb = sb + (i & 1) * BUF_SZ;
#pragma unroll
        for (int ks = 0; ks < 2; ks++) {
            uint32_t bH[4][4];
#pragma unroll
            for (int np = 0; np < 4; np++)
                ldsm4(bH[np], bufb + OFF_B_HI + (b_row + np * 640 + ks * 16) * 2);
#pragma unroll
            for (int mt = 0; mt < 4; mt++) {
                uint32_t aH[4], aL[4];
                const uint32_t ao = (a_row + mt * 640 + ks * 16) * 2;
                ldsm4(aH, bufb + OFF_A_HI + ao);
                ldsm4(aL, bufb + OFF_A_LO + ao);
#pragma unroll
                for (int nt = 0; nt < 8; nt++) {
                    const int np = nt >> 1, s = (nt & 1) * 2;
                    mma_f16(acc[mt][nt], aH, bH[np][s], bH[np][s + 1]);
                    mma_f16(acc[mt][nt], aL, bH[np][s], bH[np][s + 1]);
                }
            }
        }

        // ---- consume prefetch: bilinear + split + STS into buffer (i+1)&1 --
        if (inext < 72)
            stage_sts(inext, cwn, g00, g01, g10, g11);

        // meta for next tap (readers run after next barrier)
        if ((i & 7) == 6 && i < 64) {
            const int ntap = (i >> 3) + 1;
            if (tid < 128) compute_meta(smem, p0, tid, ntap, ntap & 1);
        }
    }

    // ---- epilogue: + bias, store ----
    const int gid = lane >> 2, tig = lane & 3;
#pragma unroll
    for (int mt = 0; mt < 4; mt++) {
        const int row0 = p0 + wm * 64 + mt * 16 + gid;
#pragma unroll
        for (int nt = 0; nt < 8; nt++) {
            const int f0 = wn * 64 + nt * 8 + 2 * tig;
            const float2 bcv = *(const float2*)(b_conv + f0);
            float2 o0, o1;
            o0.x = acc[mt][nt][0] + bcv.x;
            o0.y = acc[mt][nt][1] + bcv.y;
            o1.x = acc[mt][nt][2] + bcv.x;
            o1.y = acc[mt][nt][3] + bcv.y;
            *(float2*)(out + (size_t)row0 * Ff + f0) = o0;
            *(float2*)(out + (size_t)(row0 + 8) * Ff + f0) = o1;
        }
    }
}

// ===================== launch ==============================================
extern "C" void kernel_launch(void* const* d_in, const int* in_sizes, int n_in,
                              void* d_out, int out_size)
{
    (void)in_sizes; (void)n_in; (void)out_size;
    const float* x      = (const float*)d_in[0];
    const float* w_off  = (const float*)d_in[1];
    const float* b_off  = (const float*)d_in[2];
    const float* w_conv = (const float*)d_in[3];
    const float* b_conv = (const float*)d_in[4];
    float* out = (float*)d_out;

    cudaFuncSetAttribute(dcn_mma_kernel,
                         cudaFuncAttributeMaxDynamicSharedMemorySize, SMEM_SZ);
    cudaFuncSetAttribute(offset_mma_kernel,
                         cudaFuncAttributeMaxDynamicSharedMemorySize, OB_SMEM);

    prep_w_kernel<<<1152, 256>>>(w_conv);
    prep_woff_kernel<<<144, 256>>>(w_off);
    prep_x_kernel<<<XWORDS / 256, 256>>>(x);
    offset_mma_kernel<<<288, 256, OB_SMEM>>>(b_off);
    dcn_mma_kernel<<<288, 256, SMEM_SZ>>>(x, b_conv, out);
}

// round 10
// speedup vs baseline: 3.6695x; 1.0614x over previous
#include <cuda_runtime.h>
#include <cuda_fp16.h>
#include <math.h>
#include <stdint.h>

#define Bb 4
#define Hh 96
#define Ww 96
#define Cc 256
#define Ff 256

// ===================== mma.sync helpers =====================================
__device__ __forceinline__ uint32_t smem_u32(const void* p) {
    uint32_t a;
    asm("{ .reg .u64 t; cvta.to.shared.u64 t, %1; cvt.u32.u64 %0, t; }"
        : "=r"(a) : "l"(p));
    return a;
}
__device__ __forceinline__ void ldsm4(uint32_t* r, uint32_t addr) {
    asm volatile("ldmatrix.sync.aligned.m8n8.x4.shared.b16 {%0,%1,%2,%3}, [%4];"
        : "=r"(r[0]), "=r"(r[1]), "=r"(r[2]), "=r"(r[3]) : "r"(addr));
}
__device__ __forceinline__ void mma_f16(float* d, const uint32_t* a,
                                        uint32_t b0, uint32_t b1) {
    asm volatile(
        "mma.sync.aligned.m16n8k16.row.col.f32.f16.f16.f32 "
        "{%0,%1,%2,%3}, {%4,%5,%6,%7}, {%8,%9}, {%0,%1,%2,%3};"
        : "+f"(d[0]), "+f"(d[1]), "+f"(d[2]), "+f"(d[3])
        : "r"(a[0]), "r"(a[1]), "r"(a[2]), "r"(a[3]), "r"(b0), "r"(b1));
}
__device__ __forceinline__ uint32_t f16x2_of(float v0, float v1) {
    __half2 h = __floats2half2_rn(v0, v1);
    return *(uint32_t*)&h;
}
__device__ __forceinline__ float2 f16x2_tof(uint32_t w) {
    __half2 h = *(__half2*)&w;
    return __half22float2(h);
}
__device__ __forceinline__ void cp16(uint32_t dst, const void* src) {
    asm volatile("cp.async.cg.shared.global [%0], [%1], 16;"
                 :: "r"(dst), "l"(src));
}
__device__ __forceinline__ void cp16z(uint32_t dst, const void* src, int sz) {
    asm volatile("cp.async.cg.shared.global [%0], [%1], 16, %2;"
                 :: "r"(dst), "l"(src), "r"(sz));
}
#define CP_COMMIT() asm volatile("cp.async.commit_group;" ::: "memory")
#define CP_WAIT0()  asm volatile("cp.async.wait_group 0;" ::: "memory")
#define CP_WAIT2()  asm volatile("cp.async.wait_group 2;" ::: "memory")

// ===================== device scratch =======================================
__device__ float g_om[Bb * Hh * Ww * 27];          // dy[9], dx[9], sig(mask)[9]
__device__ uint32_t g_wbh[72 * 256 * 16];          // w_conv fp16 [chunk][f][k/2]
__device__ uint32_t g_wobh[72 * 32 * 16];          // w_off  fp16 [chunk][f][k/2]
#define XWORDS (Bb * Hh * Ww * Cc / 2)
__device__ uint32_t g_xh[XWORDS];                  // x fp16 hi
__device__ uint32_t g_xl[XWORDS];                  // x fp16 lo (residual)

// ===================== prep kernels =========================================
__global__ __launch_bounds__(256) void prep_w_kernel(const float* __restrict__ w_conv)
{
    const int g = blockIdx.x * 256 + threadIdx.x;
    const int kp = g & 15;
    const int f  = (g >> 4) & 255;
    const int chunk = g >> 12;
    const int tap = chunk >> 3, cc = chunk & 7;
    const int c = cc * 32 + 2 * kp;
    const float v0 = w_conv[((size_t)(tap * Cc + c)     * Ff) + f];
    const float v1 = w_conv[((size_t)(tap * Cc + c + 1) * Ff) + f];
    g_wbh[(chunk * 256 + f) * 16 + kp] = f16x2_of(v0, v1);
}

__global__ __launch_bounds__(256) void prep_woff_kernel(const float* __restrict__ w_off)
{
    const int g = blockIdx.x * 256 + threadIdx.x;
    const int kp = g & 15;
    const int f  = (g >> 4) & 31;
    const int chunk = g >> 9;
    const int tap = chunk >> 3, cc = chunk & 7;
    const int c = cc * 32 + 2 * kp;
    float v0 = 0.f, v1 = 0.f;
    if (f < 27) {
        v0 = w_off[((size_t)(tap * Cc + c)     * 27) + f];
        v1 = w_off[((size_t)(tap * Cc + c + 1) * 27) + f];
    }
    g_wobh[(chunk * 32 + f) * 16 + kp] = f16x2_of(v0, v1);
}

__global__ __launch_bounds__(256) void prep_x_kernel(const float* __restrict__ x)
{
    const int i = blockIdx.x * 256 + threadIdx.x;
    const float2 v = ((const float2*)x)[i];
    const uint32_t hw = f16x2_of(v.x, v.y);
    const float2 hf = f16x2_tof(hw);
    g_xh[i] = hw;
    g_xl[i] = f16x2_of(v.x - hf.x, v.y - hf.y);
}

// ===================== Kernel A: offset conv, 4-stage cp.async ring =========
#define OB_A_HI 0
#define OB_A_LO 10240
#define OB_B_HI 20480
#define OB_BUF  23040
#define OB_SMEM (4 * OB_BUF)     // 92160

__global__ __launch_bounds__(256) void offset_mma_kernel(
    const float* __restrict__ b_off)
{
    extern __shared__ __align__(16) char smem[];
    const uint32_t sb = smem_u32(smem);
    const int tid  = threadIdx.x;
    const int warp = tid >> 5;
    const int lane = tid & 31;
    const int p0 = blockIdx.x * 128;

    float acc[4][4];
#pragma unroll
    for (int nt = 0; nt < 4; nt++)
#pragma unroll
        for (int q = 0; q < 4; q++) acc[nt][q] = 0.f;

    const int spx = tid >> 1;
    const int h16 = tid & 1;
    const int p = p0 + spx;
    const int wpix = p % Ww;
    const int hw_  = p / Ww;
    const int hh = hw_ % Hh;
    const int bimg = hw_ / Hh;

    const uint32_t a_row = (uint32_t)((warp * 16 + (lane & 15)) * 40 + (lane >> 4) * 8);
    const uint32_t b_row = (uint32_t)(((lane & 7) + ((lane >> 4) << 3)) * 40
                                      + ((lane >> 3) & 1) * 8);

    auto stage = [&](int i) {
        const int tap = i >> 3, cc = i & 7;
        const uint32_t bufb = sb + (i & 3) * OB_BUF;
        const int ky = tap / 3, kx = tap % 3;
        const int y  = hh + ky - 1;
        const int xw = wpix + kx - 1;
        const bool valid = (y >= 0) && (y < Hh) && (xw >= 0) && (xw < Ww);
        const int yc = valid ? y : 0, xc = valid ? xw : 0;
        const size_t srcw = ((((size_t)(bimg * Hh + yc) * Ww + xc) * Cc)
                             + cc * 32 + h16 * 16) >> 1;
        const int sz = valid ? 16 : 0;
        const uint32_t dA = bufb + OB_A_HI + spx * 80 + h16 * 32;
        const uint32_t dL = bufb + OB_A_LO + spx * 80 + h16 * 32;
        cp16z(dA,      &g_xh[srcw],     sz);
        cp16z(dA + 16, &g_xh[srcw + 4], sz);
        cp16z(dL,      &g_xl[srcw],     sz);
        cp16z(dL + 16, &g_xl[srcw + 4], sz);
        if (tid < 64) {
            const int row = tid >> 1, bh = tid & 1;
            const size_t s2 = ((size_t)(i * 32 + row) * 16) + bh * 8;
            const uint32_t dbh = bufb + OB_B_HI + row * 80 + bh * 32;
            cp16(dbh,      &g_wobh[s2]);
            cp16(dbh + 16, &g_wobh[s2 + 4]);
        }
        CP_COMMIT();
    };

    stage(0); stage(1); stage(2);
    for (int i = 0; i < 72; i++) {
        CP_WAIT2();
        __syncthreads();
        if (i < 69) stage(i + 3);
        const uint32_t bufb = sb + (i & 3) * OB_BUF;
#pragma unroll
        for (int ks = 0; ks < 2; ks++) {
            uint32_t aH[4], aL[4], bH[2][4];
            ldsm4(aH, bufb + OB_A_HI + (a_row + ks * 16) * 2);
            ldsm4(aL, bufb + OB_A_LO + (a_row + ks * 16) * 2);
#pragma unroll
            for (int np = 0; np < 2; np++)
                ldsm4(bH[np], bufb + OB_B_HI + (b_row + np * 640 + ks * 16) * 2);
#pragma unroll
            for (int nt = 0; nt < 4; nt++) {
                const int np = nt >> 1, s = (nt & 1) * 2;
                mma_f16(acc[nt], aH, bH[np][s], bH[np][s + 1]);
                mma_f16(acc[nt], aL, bH[np][s], bH[np][s + 1]);
            }
        }
    }

    // epilogue: bias + sigmoid(mask) -> g_om
    const int gid = lane >> 2, tig = lane & 3;
    const int row0 = p0 + warp * 16 + gid;
#pragma unroll
    for (int nt = 0; nt < 4; nt++) {
        const int col = nt * 8 + 2 * tig;
#pragma unroll
        for (int e = 0; e < 2; e++) {
            const int c = col + e;
            if (c < 27) {
                const float bo = b_off[c];
                float v0 = acc[nt][e] + bo;
                float v1 = acc[nt][2 + e] + bo;
                if (c >= 18) {
                    v0 = 1.f / (1.f + expf(-v0));
                    v1 = 1.f / (1.f + expf(-v1));
                }
                g_om[(size_t)row0 * 27 + c] = v0;
                g_om[(size_t)(row0 + 8) * 27 + c] = v1;
            }
        }
    }
}

// ===================== Kernel B: deformable GEMM, fp16 hi-plane gather ======
#define BUF_SZ   40960        // A_HI|A_LO (10240 each) | B_HI (20480)
#define OFF_A_HI 0
#define OFF_A_LO 10240
#define OFF_B_HI 20480
#define OFF_META 81920        // 2 x (MW 2048 | MI 2048)
#define SMEM_SZ  90112

__device__ __forceinline__ void compute_meta(char* smem, int p0, int px,
                                             int tap, int mbuf) {
    const int p = p0 + px;
    const int wpix = p % Ww;
    const int hw_  = p / Ww;
    const int h = hw_ % Hh;
    const int b = hw_ / Hh;
    const float* om = g_om + (size_t)p * 27;
    const float dy = om[tap], dx = om[9 + tap], mask = om[18 + tap];
    const int ky = tap / 3, kx = tap % 3;
    const float ys = (float)(h + ky - 1) + dy;
    const float xs = (float)(wpix + kx - 1) + dx;
    const float y0f = floorf(ys), x0f = floorf(xs);
    const float wy1 = ys - y0f, wx1 = xs - x0f;
    const float wy0 = 1.f - wy1, wx0 = 1.f - wx1;
    const int y0 = (int)y0f, x0i = (int)x0f;
    const int y1 = y0 + 1,   x1i = x0i + 1;
    const bool vy0 = (y0  >= 0) && (y0  < Hh);
    const bool vy1 = (y1  >= 0) && (y1  < Hh);
    const bool vx0 = (x0i >= 0) && (x0i < Ww);
    const bool vx1 = (x1i >= 0) && (x1i < Ww);
    const float c00 = (vy0 && vx0) ? wy0 * wx0 * mask : 0.f;
    const float c01 = (vy0 && vx1) ? wy0 * wx1 * mask : 0.f;
    const float c10 = (vy1 && vx0) ? wy1 * wx0 * mask : 0.f;
    const float c11 = (vy1 && vx1) ? wy1 * wx1 * mask : 0.f;
    const int y0c = min(max(y0, 0), Hh - 1), y1c = min(max(y1, 0), Hh - 1);
    const int x0c = min(max(x0i, 0), Ww - 1), x1c = min(max(x1i, 0), Ww - 1);
    const int r0 = (b * Hh + y0c) * Ww, r1 = (b * Hh + y1c) * Ww;
    char* mb = smem + OFF_META + mbuf * 4096;
    *(float4*)(mb + px * 16) = make_float4(c00, c01, c10, c11);
    // pair-word indices into g_xh (float index / 2)
    *(int4*)(mb + 2048 + px * 16) =
        make_int4(((r0 + x0c) * Cc) >> 1, ((r0 + x1c) * Cc) >> 1,
                  ((r1 + x0c) * Cc) >> 1, ((r1 + x1c) * Cc) >> 1);
}

__global__ __launch_bounds__(256, 1) void dcn_mma_kernel(
    const float* __restrict__ b_conv, float* __restrict__ out)
{
    extern __shared__ __align__(16) char smem[];
    const uint32_t sb = smem_u32(smem);

    const int tid  = threadIdx.x;
    const int warp = tid >> 5;
    const int lane = tid & 31;
    const int wm = warp >> 2;
    const int wn = warp & 3;
    const int p0 = blockIdx.x * 128;

    float acc[4][8][4];
#pragma unroll
    for (int mt = 0; mt < 4; mt++)
#pragma unroll
        for (int nt = 0; nt < 8; nt++)
#pragma unroll
            for (int q = 0; q < 4; q++) acc[mt][nt][q] = 0.f;

    const uint32_t a_row = (uint32_t)((wm * 64 + (lane & 15)) * 40 + (lane >> 4) * 8);
    const uint32_t b_row = (uint32_t)((wn * 64 + (lane & 7) + ((lane >> 4) << 3)) * 40
                                      + ((lane >> 3) & 1) * 8);

    const int spx   = tid >> 1;      // staging pixel
    const int chalf = tid & 1;       // staging channel half (16 c = 8 pair-words)

    // B copy for chunk i into buffer (i&1)
    auto stage_b = [&](int i) {
#pragma unroll
        for (int t2 = 0; t2 < 2; t2++) {
            const int pid = tid + t2 * 256;
            const int row = pid >> 1, bh = pid & 1;
            const size_t src = ((size_t)(i * 256 + row) * 16) + bh * 8;
            const uint32_t dH = sb + (i & 1) * BUF_SZ + OFF_B_HI + row * 80 + bh * 32;
            cp16(dH,      &g_wbh[src]);
            cp16(dH + 16, &g_wbh[src + 4]);
        }
        CP_COMMIT();
    };
    // convert + STS of prefetched fp16 gather for chunk i
    auto stage_sts = [&](int i, const float4 cw,
                         const uint4* c00, const uint4* c01,
                         const uint4* c10, const uint4* c11) {
        char* buf = smem + (i & 1) * BUF_SZ;
        const uint32_t sbase = (uint32_t)(spx * 80 + chalf * 32);
#pragma unroll
        for (int u = 0; u < 2; u++) {
            uint32_t hw[4], lw[4];
            const uint32_t* w00 = (const uint32_t*)&c00[u];
            const uint32_t* w01 = (const uint32_t*)&c01[u];
            const uint32_t* w10 = (const uint32_t*)&c10[u];
            const uint32_t* w11 = (const uint32_t*)&c11[u];
#pragma unroll
            for (int j = 0; j < 4; j++) {
                const float2 f00 = f16x2_tof(w00[j]);
                const float2 f01 = f16x2_tof(w01[j]);
                const float2 f10 = f16x2_tof(w10[j]);
                const float2 f11 = f16x2_tof(w11[j]);
                const float v0 = cw.x*f00.x + cw.y*f01.x + cw.z*f10.x + cw.w*f11.x;
                const float v1 = cw.x*f00.y + cw.y*f01.y + cw.z*f10.y + cw.w*f11.y;
                hw[j] = f16x2_of(v0, v1);
                const float2 hf = f16x2_tof(hw[j]);
                lw[j] = f16x2_of(v0 - hf.x, v1 - hf.y);
            }
            *(uint4*)(buf + OFF_A_HI + sbase + u * 16) =
                make_uint4(hw[0], hw[1], hw[2], hw[3]);
            *(uint4*)(buf + OFF_A_LO + sbase + u * 16) =
                make_uint4(lw[0], lw[1], lw[2], lw[3]);
        }
    };

    // ---- prologue: meta(0), full stage of chunk 0 ----
    if (tid < 128) compute_meta(smem, p0, tid, 0, 0);
    __syncthreads();
    {
        const char* mb = smem + OFF_META;
        const float4 cw = *(const float4*)(mb + spx * 16);
        const int4   ai = *(const int4*)(mb + 2048 + spx * 16);
        const int cgp = chalf * 8;   // chunk 0: cc=0; pair-word offset
        uint4 c00[2], c01[2], c10[2], c11[2];
#pragma unroll
        for (int u = 0; u < 2; u++) {
            c00[u] = *(const uint4*)(g_xh + ai.x + cgp + 4 * u);
            c01[u] = *(const uint4*)(g_xh + ai.y + cgp + 4 * u);
            c10[u] = *(const uint4*)(g_xh + ai.z + cgp + 4 * u);
            c11[u] = *(const uint4*)(g_xh + ai.w + cgp + 4 * u);
        }
        stage_sts(0, cw, c00, c01, c10, c11);
        stage_b(0);
    }

    for (int i = 0; i < 72; i++) {
        CP_WAIT0();
        __syncthreads();

        // prefetch fp16 gather for i+1 into registers; launch B copy for i+1
        uint4 c00[2], c01[2], c10[2], c11[2];
        float4 cwn;
        const int inext = i + 1;
        if (inext < 72) {
            const int tapn = inext >> 3, ccn = inext & 7;
            const char* mb = smem + OFF_META + (tapn & 1) * 4096;
            cwn = *(const float4*)(mb + spx * 16);
            const int4 ain = *(const int4*)(mb + 2048 + spx * 16);
            const int cgp = ccn * 16 + chalf * 8;   // pair-word offset
#pragma unroll
            for (int u = 0; u < 2; u++) {
                c00[u] = *(const uint4*)(g_xh + ain.x + cgp + 4 * u);
                c01[u] = *(const uint4*)(g_xh + ain.y + cgp + 4 * u);
                c10[u] = *(const uint4*)(g_xh + ain.z + cgp + 4 * u);
                c11[u] = *(const uint4*)(g_xh + ain.w + cgp + 4 * u);
            }
            stage_b(inext);
        }

        // ---- MMA burst for chunk i (hides prefetch LDG latency) ----
        const uint32_t bufb = sb + (i & 1) * BUF_SZ;
#pragma unroll
        for (int ks = 0; ks < 2; ks++) {
            uint32_t bH[4][4];
#pragma unroll
            for (int np = 0; np < 4; np++)
                ldsm4(bH[np], bufb + OFF_B_HI + (b_row + np * 640 + ks * 16) * 2);
#pragma unroll
            for (int mt = 0; mt < 4; mt++) {
                uint32_t aH[4], aL[4];
                const uint32_t ao = (a_row + mt * 640 + ks * 16) * 2;
                ldsm4(aH, bufb + OFF_A_HI + ao);
                ldsm4(aL, bufb + OFF_A_LO + ao);
#pragma unroll
                for (int nt = 0; nt < 8; nt++) {
                    const int np = nt >> 1, s = (nt & 1) * 2;
                    mma_f16(acc[mt][nt], aH, bH[np][s], bH[np][s + 1]);
                    mma_f16(acc[mt][nt], aL, bH[np][s], bH[np][s + 1]);
                }
            }
        }

        // ---- consume prefetch: bilinear + split + STS into buffer (i+1)&1 --
        if (inext < 72)
            stage_sts(inext, cwn, c00, c01, c10, c11);

        // meta for next tap (readers run after next barrier)
        if ((i & 7) == 6 && i < 64) {
            const int ntap = (i >> 3) + 1;
            if (tid < 128) compute_meta(smem, p0, tid, ntap, ntap & 1);
        }
    }

    // ---- epilogue: + bias, store ----
    const int gid = lane >> 2, tig = lane & 3;
#pragma unroll
    for (int mt = 0; mt < 4; mt++) {
        const int row0 = p0 + wm * 64 + mt * 16 + gid;
#pragma unroll
        for (int nt = 0; nt < 8; nt++) {
            const int f0 = wn * 64 + nt * 8 + 2 * tig;
            const float2 bcv = *(const float2*)(b_conv + f0);
            float2 o0, o1;
            o0.x = acc[mt][nt][0] + bcv.x;
            o0.y = acc[mt][nt][1] + bcv.y;
            o1.x = acc[mt][nt][2] + bcv.x;
            o1.y = acc[mt][nt][3] + bcv.y;
            *(float2*)(out + (size_t)row0 * Ff + f0) = o0;
            *(float2*)(out + (size_t)(row0 + 8) * Ff + f0) = o1;
        }
    }
}

// ===================== launch ==============================================
extern "C" void kernel_launch(void* const* d_in, const int* in_sizes, int n_in,
                              void* d_out, int out_size)
{
    (void)in_sizes; (void)n_in; (void)out_size;
    const float* x      = (const float*)d_in[0];
    const float* w_off  = (const float*)d_in[1];
    const float* b_off  = (const float*)d_in[2];
    const float* w_conv = (const float*)d_in[3];
    const float* b_conv = (const float*)d_in[4];
    float* out = (float*)d_out;

    cudaFuncSetAttribute(dcn_mma_kernel,
                         cudaFuncAttributeMaxDynamicSharedMemorySize, SMEM_SZ);
    cudaFuncSetAttribute(offset_mma_kernel,
                         cudaFuncAttributeMaxDynamicSharedMemorySize, OB_SMEM);

    prep_w_kernel<<<1152, 256>>>(w_conv);
    prep_woff_kernel<<<144, 256>>>(w_off);
    prep_x_kernel<<<XWORDS / 256, 256>>>(x);
    offset_mma_kernel<<<288, 256, OB_SMEM>>>(b_off);
    dcn_mma_kernel<<<288, 256, SMEM_SZ>>>(b_conv, out);
}